// round 5
// baseline (speedup 1.0000x reference)
#include <cuda_runtime.h>

#define ALPHA 0.2f

// Shapes (fixed by the problem)
#define NB   2048      // batch
#define NL   128       // neighbors
#define ND   512       // IN_DIM
#define NH   512       // HID

// Scratch (device globals: allocation-free by harness rules)
__device__ __align__(16) float g_xh[NB * NH];                       // 4 MB
__device__ __align__(16) float g_q [NB * NH];                       // 4 MB
__device__ __align__(16) float g_yh[(size_t)NB * NL * NH];          // 512 MB

__device__ __forceinline__ unsigned f2tf32(float x) {
    unsigned r;
    asm("cvt.rna.tf32.f32 %0, %1;" : "=r"(r) : "f"(x));
    return r;
}

__device__ __forceinline__ void mma_tf32(float c[4],
                                         unsigned a0, unsigned a1, unsigned a2, unsigned a3,
                                         unsigned b0, unsigned b1) {
    asm volatile(
        "mma.sync.aligned.m16n8k8.row.col.f32.tf32.tf32.f32 "
        "{%0,%1,%2,%3}, {%4,%5,%6,%7}, {%8,%9}, {%0,%1,%2,%3};\n"
        : "+f"(c[0]), "+f"(c[1]), "+f"(c[2]), "+f"(c[3])
        : "r"(a0), "r"(a1), "r"(a2), "r"(a3), "r"(b0), "r"(b1));
}

__device__ __forceinline__ float lrelu(float v) { return v > 0.0f ? v : ALPHA * v; }

// ---------------------------------------------------------------------------
// Generic C[M,512] = act(A[M,512] @ W[512,512]^T + bias), act: 0=none 1=lrelu
// CTA tile 128(M) x 64(N), K chunks of 32, tf32 mma. 256 threads, 8 warps 4x2.
// grid = (8, M/128): n-tile fast -> A tile reused from L2 across 8 n-tiles.
// ---------------------------------------------------------------------------
__global__ __launch_bounds__(256) void gemm512_act(
    const float* __restrict__ A, const float* __restrict__ W,
    const float* __restrict__ bias, float* __restrict__ C, int act)
{
    __shared__ unsigned As[128][36];   // tf32 bits, padded stride
    __shared__ unsigned Ws[64][36];

    const int tid  = threadIdx.x;
    const int warp = tid >> 5, lane = tid & 31;
    const int g = lane >> 2, t = lane & 3;
    const int wm = warp & 3, wn = warp >> 2;          // 4 x 2 warp grid
    const int m0 = blockIdx.y * 128;
    const int n0 = blockIdx.x * 64;

    float acc[2][4][4];
#pragma unroll
    for (int mf = 0; mf < 2; mf++)
#pragma unroll
        for (int nf = 0; nf < 4; nf++)
#pragma unroll
            for (int i = 0; i < 4; i++) acc[mf][nf][i] = 0.0f;

    for (int k0 = 0; k0 < ND; k0 += 32) {
        // A chunk: 128 x 32 floats, 4 float4 per thread
#pragma unroll
        for (int i = 0; i < 4; i++) {
            int idx = i * 256 + tid;
            int r = idx >> 3, c4 = (idx & 7) * 4;
            float4 v = *reinterpret_cast<const float4*>(&A[(size_t)(m0 + r) * ND + k0 + c4]);
            uint4 u = make_uint4(f2tf32(v.x), f2tf32(v.y), f2tf32(v.z), f2tf32(v.w));
            *reinterpret_cast<uint4*>(&As[r][c4]) = u;
        }
        // W chunk: 64 x 32 floats, 2 float4 per thread
#pragma unroll
        for (int i = 0; i < 2; i++) {
            int idx = i * 256 + tid;
            int r = idx >> 3, c4 = (idx & 7) * 4;
            float4 v = *reinterpret_cast<const float4*>(&W[(size_t)(n0 + r) * ND + k0 + c4]);
            uint4 u = make_uint4(f2tf32(v.x), f2tf32(v.y), f2tf32(v.z), f2tf32(v.w));
            *reinterpret_cast<uint4*>(&Ws[r][c4]) = u;
        }
        __syncthreads();

#pragma unroll
        for (int ks = 0; ks < 32; ks += 8) {
            unsigned a[2][4], b[4][2];
#pragma unroll
            for (int mf = 0; mf < 2; mf++) {
                int r0 = wm * 32 + mf * 16 + g;
                a[mf][0] = As[r0    ][ks + t];
                a[mf][1] = As[r0 + 8][ks + t];
                a[mf][2] = As[r0    ][ks + t + 4];
                a[mf][3] = As[r0 + 8][ks + t + 4];
            }
#pragma unroll
            for (int nf = 0; nf < 4; nf++) {
                int c0 = wn * 32 + nf * 8 + g;
                b[nf][0] = Ws[c0][ks + t];
                b[nf][1] = Ws[c0][ks + t + 4];
            }
#pragma unroll
            for (int mf = 0; mf < 2; mf++)
#pragma unroll
                for (int nf = 0; nf < 4; nf++)
                    mma_tf32(acc[mf][nf], a[mf][0], a[mf][1], a[mf][2], a[mf][3],
                             b[nf][0], b[nf][1]);
        }
        __syncthreads();
    }

    // Epilogue: bias + optional lrelu, coalesced float2 stores
#pragma unroll
    for (int mf = 0; mf < 2; mf++) {
        int row = m0 + wm * 32 + mf * 16 + g;
#pragma unroll
        for (int nf = 0; nf < 4; nf++) {
            int col = n0 + wn * 32 + nf * 8 + 2 * t;
            float b0 = bias[col], b1 = bias[col + 1];
            float v0 = acc[mf][nf][0] + b0;
            float v1 = acc[mf][nf][1] + b1;
            float v2 = acc[mf][nf][2] + b0;
            float v3 = acc[mf][nf][3] + b1;
            if (act) { v0 = lrelu(v0); v1 = lrelu(v1); v2 = lrelu(v2); v3 = lrelu(v3); }
            *reinterpret_cast<float2*>(&C[(size_t)row * NH + col])       = make_float2(v0, v1);
            *reinterpret_cast<float2*>(&C[(size_t)(row + 8) * NH + col]) = make_float2(v2, v3);
        }
    }
}

// ---------------------------------------------------------------------------
// Fused key/vec GEMM + softmax-over-L epilogue.
// CTA = (batch b, feature tile ht of 64). Computes [128L x 128] where cols
// 0..63 = key(h), 64..127 = vec(h), h = ht*64 + j. Then per-column softmax
// over L and lrelu-weighted sum, out = (xh + h)/2.
// grid = (8, 2048) with ht fast so yh_b stays in L2 across its 8 CTAs.
// Dynamic SMEM: mainloop 2*128*36*4 = 36864 B; epilogue tile 128*132*4 = 67584 B.
// ---------------------------------------------------------------------------
__global__ __launch_bounds__(256) void attn_fused(
    const float* __restrict__ kw, const float* __restrict__ kb,
    const float* __restrict__ vw, const float* __restrict__ vb,
    float* __restrict__ out)
{
    extern __shared__ char smem[];
    unsigned (*As)[36] = reinterpret_cast<unsigned (*)[36]>(smem);
    unsigned (*Ws)[36] = reinterpret_cast<unsigned (*)[36]>(smem + 128 * 36 * 4);
    float    (*Ct)[132] = reinterpret_cast<float (*)[132]>(smem);   // epilogue reuse

    const int tid  = threadIdx.x;
    const int warp = tid >> 5, lane = tid & 31;
    const int g = lane >> 2, t = lane & 3;
    const int wm = warp & 1, wn = warp >> 1;          // 2 x 4 warp grid
    const int bb = blockIdx.y;
    const int hbase = blockIdx.x * 64;
    const float* Ab = g_yh + (size_t)bb * NL * NH;

    float acc[4][4][4];
#pragma unroll
    for (int mf = 0; mf < 4; mf++)
#pragma unroll
        for (int nf = 0; nf < 4; nf++)
#pragma unroll
            for (int i = 0; i < 4; i++) acc[mf][nf][i] = 0.0f;

    for (int k0 = 0; k0 < NH; k0 += 32) {
#pragma unroll
        for (int i = 0; i < 4; i++) {
            int idx = i * 256 + tid;
            int r = idx >> 3, c4 = (idx & 7) * 4;
            float4 v = *reinterpret_cast<const float4*>(&Ab[(size_t)r * NH + k0 + c4]);
            uint4 u = make_uint4(f2tf32(v.x), f2tf32(v.y), f2tf32(v.z), f2tf32(v.w));
            *reinterpret_cast<uint4*>(&As[r][c4]) = u;
        }
#pragma unroll
        for (int i = 0; i < 4; i++) {
            int idx = i * 256 + tid;
            int r = idx >> 3, c4 = (idx & 7) * 4;
            const float* wr = (r < 64) ? (kw + (size_t)(hbase + r) * NH)
                                       : (vw + (size_t)(hbase + r - 64) * NH);
            float4 v = *reinterpret_cast<const float4*>(&wr[k0 + c4]);
            uint4 u = make_uint4(f2tf32(v.x), f2tf32(v.y), f2tf32(v.z), f2tf32(v.w));
            *reinterpret_cast<uint4*>(&Ws[r][c4]) = u;
        }
        __syncthreads();

#pragma unroll
        for (int ks = 0; ks < 32; ks += 8) {
            unsigned a[4][4], b[4][2];
#pragma unroll
            for (int mf = 0; mf < 4; mf++) {
                int r0 = wm * 64 + mf * 16 + g;
                a[mf][0] = As[r0    ][ks + t];
                a[mf][1] = As[r0 + 8][ks + t];
                a[mf][2] = As[r0    ][ks + t + 4];
                a[mf][3] = As[r0 + 8][ks + t + 4];
            }
#pragma unroll
            for (int nf = 0; nf < 4; nf++) {
                int c0 = wn * 32 + nf * 8 + g;
                b[nf][0] = Ws[c0][ks + t];
                b[nf][1] = Ws[c0][ks + t + 4];
            }
#pragma unroll
            for (int mf = 0; mf < 4; mf++)
#pragma unroll
                for (int nf = 0; nf < 4; nf++)
                    mma_tf32(acc[mf][nf], a[mf][0], a[mf][1], a[mf][2], a[mf][3],
                             b[nf][0], b[nf][1]);
        }
        __syncthreads();
    }

    // Stage the full 128x128 key|vec tile in SMEM (aliases As/Ws — all reads done)
#pragma unroll
    for (int mf = 0; mf < 4; mf++) {
        int row = wm * 64 + mf * 16 + g;
#pragma unroll
        for (int nf = 0; nf < 4; nf++) {
            int col = wn * 32 + nf * 8 + 2 * t;
            Ct[row    ][col]     = acc[mf][nf][0];
            Ct[row    ][col + 1] = acc[mf][nf][1];
            Ct[row + 8][col]     = acc[mf][nf][2];
            Ct[row + 8][col + 1] = acc[mf][nf][3];
        }
    }
    __syncthreads();

    // Softmax over L per feature column. 4 threads per column, 32 rows each.
    const int j = tid >> 2;          // 0..63
    const int p = tid & 3;           // row partition
    const int h = hbase + j;
    const float qv  = g_q[(size_t)bb * NH + h];
    const float kbv = kb[h];
    const float vbv = vb[h];

    float mloc = -1e30f;
#pragma unroll 8
    for (int i = 0; i < 32; i++) {
        int l = p * 32 + i;
        float att = (Ct[l][j] + kbv) * qv;
        mloc = fmaxf(mloc, att);
    }
    mloc = fmaxf(mloc, __shfl_xor_sync(0xffffffffu, mloc, 1));
    mloc = fmaxf(mloc, __shfl_xor_sync(0xffffffffu, mloc, 2));

    float sloc = 0.0f;
#pragma unroll 8
    for (int i = 0; i < 32; i++) {
        int l = p * 32 + i;
        float att = (Ct[l][j] + kbv) * qv;
        sloc += __expf(att - mloc);
    }
    sloc += __shfl_xor_sync(0xffffffffu, sloc, 1);
    sloc += __shfl_xor_sync(0xffffffffu, sloc, 2);
    const float inv_s = 1.0f / sloc;

    float hloc = 0.0f;
#pragma unroll 8
    for (int i = 0; i < 32; i++) {
        int l = p * 32 + i;
        float att = (Ct[l][j] + kbv) * qv;
        float e = __expf(att - mloc) * inv_s;
        float val = (Ct[l][j + 64] + vbv) * e;
        hloc += lrelu(val);
    }
    hloc += __shfl_xor_sync(0xffffffffu, hloc, 1);
    hloc += __shfl_xor_sync(0xffffffffu, hloc, 2);

    if (p == 0)
        out[(size_t)bb * NH + h] = (g_xh[(size_t)bb * NH + h] + hloc) * 0.5f;
}

// ---------------------------------------------------------------------------
extern "C" void kernel_launch(void* const* d_in, const int* in_sizes, int n_in,
                              void* d_out, int out_size)
{
    (void)in_sizes; (void)n_in; (void)out_size;
    const float* x    = (const float*)d_in[0];
    const float* y    = (const float*)d_in[1];
    const float* fc_w = (const float*)d_in[2];
    const float* fc_b = (const float*)d_in[3];
    const float* q_w  = (const float*)d_in[4];
    const float* q_b  = (const float*)d_in[5];
    const float* k_w  = (const float*)d_in[6];
    const float* k_b  = (const float*)d_in[7];
    const float* v_w  = (const float*)d_in[8];
    const float* v_b  = (const float*)d_in[9];
    float* out = (float*)d_out;

    float *p_xh, *p_q, *p_yh;
    cudaGetSymbolAddress((void**)&p_xh, g_xh);
    cudaGetSymbolAddress((void**)&p_q,  g_q);
    cudaGetSymbolAddress((void**)&p_yh, g_yh);

    const int SMEM_K3 = 128 * 132 * 4;   // 67584 B (> mainloop's 36864 B)
    cudaFuncSetAttribute(attn_fused, cudaFuncAttributeMaxDynamicSharedMemorySize, SMEM_K3);

    // 1) xh = lrelu(x @ fc_w^T + fc_b)            [2048, 512]
    gemm512_act<<<dim3(8, NB / 128), 256>>>(x, fc_w, fc_b, p_xh, 1);
    // 2) q = xh @ q_w^T + q_b                     [2048, 512]
    gemm512_act<<<dim3(8, NB / 128), 256>>>(p_xh, q_w, q_b, p_q, 0);
    // 3) yh = lrelu(y @ fc_w^T + fc_b)            [262144, 512]
    gemm512_act<<<dim3(8, (NB * NL) / 128), 256>>>(y, fc_w, fc_b, p_yh, 1);
    // 4) key/vec GEMM + softmax epilogue -> out
    attn_fused<<<dim3(8, NB), 256, SMEM_K3>>>(k_w, k_b, v_w, v_b, out);
}

// round 7
// speedup vs baseline: 1.2748x; 1.2748x over previous
#include <cuda_runtime.h>
#include <cuda_fp16.h>
#include <cstdint>

#define ALPHA 0.2f

// Shapes (fixed by the problem)
#define NB   2048      // batch
#define NL   128       // neighbors
#define ND   512       // IN_DIM
#define NH   512       // HID

// Scratch (device globals: allocation-free by harness rules)
__device__ __align__(16) float  g_xh[NB * NH];                      // 4 MB
__device__ __align__(16) float  g_q [NB * NH];                      // 4 MB
__device__ __align__(16) __half g_yh[(size_t)NB * NL * NH];         // 256 MB

// ===========================================================================
// Helpers
// ===========================================================================
__device__ __forceinline__ float lrelu(float v) { return v > 0.0f ? v : ALPHA * v; }

__device__ __forceinline__ unsigned f2tf32(float x) {
    unsigned r;
    asm("cvt.rna.tf32.f32 %0, %1;" : "=r"(r) : "f"(x));
    return r;
}
__device__ __forceinline__ unsigned pack2(float a, float b) {
    __half2 h = __floats2half2_rn(a, b);
    return reinterpret_cast<unsigned&>(h);
}
__device__ __forceinline__ uint32_t smem_u32(const void* p) {
    uint32_t a;
    asm("{ .reg .u64 t; cvta.to.shared.u64 t, %1; cvt.u32.u64 %0, t; }" : "=r"(a) : "l"(p));
    return a;
}
__device__ __forceinline__ void ldmx4(uint32_t r[4], uint32_t addr) {
    asm volatile("ldmatrix.sync.aligned.m8n8.x4.shared.b16 {%0,%1,%2,%3}, [%4];"
                 : "=r"(r[0]), "=r"(r[1]), "=r"(r[2]), "=r"(r[3]) : "r"(addr));
}
__device__ __forceinline__ void mma_f16(float c[4], const uint32_t a[4],
                                        uint32_t b0, uint32_t b1) {
    asm volatile("mma.sync.aligned.m16n8k16.row.col.f32.f16.f16.f32 "
                 "{%0,%1,%2,%3}, {%4,%5,%6,%7}, {%8,%9}, {%0,%1,%2,%3};"
                 : "+f"(c[0]), "+f"(c[1]), "+f"(c[2]), "+f"(c[3])
                 : "r"(a[0]), "r"(a[1]), "r"(a[2]), "r"(a[3]), "r"(b0), "r"(b1));
}

// SW128-style swizzle for fp16 tiles: 128 rows x 64 halves (128B rows).
// 16B segment s of row r lands at segment (s ^ (r&7)).
// ldmatrix address for an 8x8 tile at (rowbase, colbyte): per-lane.
__device__ __forceinline__ uint32_t ldm_addr(uint32_t base, int rowbase, int colbyte, int lane) {
    int mi = lane >> 3;
    int r  = rowbase + (mi & 1) * 8 + (lane & 7);
    unsigned off = (unsigned)(r * 128 + colbyte + (mi >> 1) * 16);
    return base + (off ^ ((off >> 3) & 0x70));
}

// SMEM layout for fp16 GEMM kernels (all offsets from 128B-aligned base):
//   A bufs: 0, 16384   B bufs: 32768, 49152   (16 KB each)
#define BUF_A(i) ((i) * 16384)
#define BUF_B(i) (32768 + (i) * 16384)
#define SMEM_MAIN 65536
#define NCH 8                   // K=512 in chunks of 64 halves

// ===========================================================================
// Kernel: yh = lrelu(y @ fc_w^T + fc_b) -> fp16.  CTA tile 128x128, K=512.
// grid = (4, 2048), x = n-tile (fast) for A-tile L2 reuse.
// ===========================================================================
__global__ __launch_bounds__(256) void yh_fp16(
    const float* __restrict__ A, const float* __restrict__ W,
    const float* __restrict__ bias, __half* __restrict__ C)
{
    extern __shared__ char smem_raw[];
    char* sm = smem_raw + ((128 - ((uintptr_t)smem_raw & 127)) & 127);
    const uint32_t sb = smem_u32(sm);

    const int tid = threadIdx.x, warp = tid >> 5, lane = tid & 31;
    const int g = lane >> 2, t = lane & 3;
    const int wm = warp & 1, wn = warp >> 1;           // 2 x 4 warp grid
    const int m0 = blockIdx.y * 128;
    const int n0 = blockIdx.x * 128;
    const float* Ab = A + (size_t)m0 * ND;
    const float* Wb = W + (size_t)n0 * ND;

    float acc[4][4][4];
#pragma unroll
    for (int mf = 0; mf < 4; mf++)
#pragma unroll
        for (int nf = 0; nf < 4; nf++)
#pragma unroll
            for (int i = 0; i < 4; i++) acc[mf][nf][i] = 0.0f;

    uint4 ra[4], rb[4];

    auto ldg = [&](int c) {
#pragma unroll
        for (int i = 0; i < 4; i++) {
            int idx = i * 256 + tid;
            int r = idx >> 3, s = idx & 7;
            const float* pa = Ab + (size_t)r * ND + c * 64 + s * 8;
            float4 a0 = *reinterpret_cast<const float4*>(pa);
            float4 a1 = *reinterpret_cast<const float4*>(pa + 4);
            ra[i] = make_uint4(pack2(a0.x, a0.y), pack2(a0.z, a0.w),
                               pack2(a1.x, a1.y), pack2(a1.z, a1.w));
            const float* pb = Wb + (size_t)r * ND + c * 64 + s * 8;
            float4 b0 = *reinterpret_cast<const float4*>(pb);
            float4 b1 = *reinterpret_cast<const float4*>(pb + 4);
            rb[i] = make_uint4(pack2(b0.x, b0.y), pack2(b0.z, b0.w),
                               pack2(b1.x, b1.y), pack2(b1.z, b1.w));
        }
    };
    auto sts = [&](int buf) {
#pragma unroll
        for (int i = 0; i < 4; i++) {
            int idx = i * 256 + tid;
            int r = idx >> 3, s = idx & 7;
            unsigned off = (unsigned)(r * 128 + ((s ^ (r & 7)) * 16));
            *reinterpret_cast<uint4*>(sm + BUF_A(buf) + off) = ra[i];
            *reinterpret_cast<uint4*>(sm + BUF_B(buf) + off) = rb[i];
        }
    };
    auto mmac = [&](int buf) {
        const uint32_t Abase = sb + BUF_A(buf), Bbase = sb + BUF_B(buf);
#pragma unroll
        for (int ks = 0; ks < 4; ks++) {
            uint32_t a[4][4], b[2][4];
#pragma unroll
            for (int mf = 0; mf < 4; mf++)
                ldmx4(a[mf], ldm_addr(Abase, wm * 64 + mf * 16, ks * 32, lane));
#pragma unroll
            for (int np = 0; np < 2; np++)
                ldmx4(b[np], ldm_addr(Bbase, wn * 32 + np * 16, ks * 32, lane));
#pragma unroll
            for (int mf = 0; mf < 4; mf++)
#pragma unroll
                for (int nf = 0; nf < 4; nf++)
                    mma_f16(acc[mf][nf], a[mf], b[nf >> 1][nf & 1], b[nf >> 1][(nf & 1) + 2]);
        }
    };

    ldg(0); sts(0); __syncthreads();
    ldg(1);
    for (int c = 0; c < NCH; c++) {
        mmac(c & 1);
        if (c + 1 < NCH) {
            __syncthreads();
            sts((c + 1) & 1);
            __syncthreads();
            if (c + 2 < NCH) ldg(c + 2);
        }
    }

    // Epilogue: bias + lrelu -> half2 stores straight to gmem
#pragma unroll
    for (int mf = 0; mf < 4; mf++) {
        int row = m0 + wm * 64 + mf * 16 + g;
#pragma unroll
        for (int nf = 0; nf < 4; nf++) {
            int col = n0 + wn * 32 + nf * 8 + 2 * t;
            float b0 = bias[col], b1 = bias[col + 1];
            __half2 h0 = __floats2half2_rn(lrelu(acc[mf][nf][0] + b0),
                                           lrelu(acc[mf][nf][1] + b1));
            __half2 h1 = __floats2half2_rn(lrelu(acc[mf][nf][2] + b0),
                                           lrelu(acc[mf][nf][3] + b1));
            *reinterpret_cast<__half2*>(&C[(size_t)row * NH + col])       = h0;
            *reinterpret_cast<__half2*>(&C[(size_t)(row + 8) * NH + col]) = h1;
        }
    }
}

// ===========================================================================
// Kernel: fused key/vec GEMM (fp16 mma + ldmatrix) + softmax-over-L epilogue.
// CTA = (batch, 64-feature tile). C cols 0..63 = key, 64..127 = vec.
// grid = (8, 2048), x fast so yh_b (128 KB fp16) stays in L2 across its 8 CTAs.
// ===========================================================================
__global__ __launch_bounds__(256) void attn_fp16(
    const float* __restrict__ kw, const float* __restrict__ kb,
    const float* __restrict__ vw, const float* __restrict__ vb,
    float* __restrict__ out)
{
    extern __shared__ char smem_raw[];
    char* sm = smem_raw + ((128 - ((uintptr_t)smem_raw & 127)) & 127);
    const uint32_t sb = smem_u32(sm);

    const int tid = threadIdx.x, warp = tid >> 5, lane = tid & 31;
    const int g = lane >> 2, t = lane & 3;
    const int wm = warp & 1, wn = warp >> 1;           // 2 x 4 warp grid
    const int bb = blockIdx.y;
    const int hbase = blockIdx.x * 64;
    const __half* Ab = g_yh + (size_t)bb * NL * NH;

    float acc[4][4][4];
#pragma unroll
    for (int mf = 0; mf < 4; mf++)
#pragma unroll
        for (int nf = 0; nf < 4; nf++)
#pragma unroll
            for (int i = 0; i < 4; i++) acc[mf][nf][i] = 0.0f;

    uint4 ra[4], rb[4];

    auto ldg = [&](int c) {
#pragma unroll
        for (int i = 0; i < 4; i++) {
            int idx = i * 256 + tid;
            int r = idx >> 3, s = idx & 7;
            // A is already fp16 in gmem
            ra[i] = *reinterpret_cast<const uint4*>(Ab + (size_t)r * NH + c * 64 + s * 8);
            const float* wr = (r < 64) ? (kw + (size_t)(hbase + r) * NH)
                                       : (vw + (size_t)(hbase + r - 64) * NH);
            const float* pb = wr + c * 64 + s * 8;
            float4 b0 = *reinterpret_cast<const float4*>(pb);
            float4 b1 = *reinterpret_cast<const float4*>(pb + 4);
            rb[i] = make_uint4(pack2(b0.x, b0.y), pack2(b0.z, b0.w),
                               pack2(b1.x, b1.y), pack2(b1.z, b1.w));
        }
    };
    auto sts = [&](int buf) {
#pragma unroll
        for (int i = 0; i < 4; i++) {
            int idx = i * 256 + tid;
            int r = idx >> 3, s = idx & 7;
            unsigned off = (unsigned)(r * 128 + ((s ^ (r & 7)) * 16));
            *reinterpret_cast<uint4*>(sm + BUF_A(buf) + off) = ra[i];
            *reinterpret_cast<uint4*>(sm + BUF_B(buf) + off) = rb[i];
        }
    };
    auto mmac = [&](int buf) {
        const uint32_t Abase = sb + BUF_A(buf), Bbase = sb + BUF_B(buf);
#pragma unroll
        for (int ks = 0; ks < 4; ks++) {
            uint32_t a[4][4], b[2][4];
#pragma unroll
            for (int mf = 0; mf < 4; mf++)
                ldmx4(a[mf], ldm_addr(Abase, wm * 64 + mf * 16, ks * 32, lane));
#pragma unroll
            for (int np = 0; np < 2; np++)
                ldmx4(b[np], ldm_addr(Bbase, wn * 32 + np * 16, ks * 32, lane));
#pragma unroll
            for (int mf = 0; mf < 4; mf++)
#pragma unroll
                for (int nf = 0; nf < 4; nf++)
                    mma_f16(acc[mf][nf], a[mf], b[nf >> 1][nf & 1], b[nf >> 1][(nf & 1) + 2]);
        }
    };

    ldg(0); sts(0); __syncthreads();
    ldg(1);
    for (int c = 0; c < NCH; c++) {
        mmac(c & 1);
        if (c + 1 < NCH) {
            __syncthreads();
            sts((c + 1) & 1);
            __syncthreads();
            if (c + 2 < NCH) ldg(c + 2);
        }
    }
    __syncthreads();   // all reads of the mainloop buffers done; alias with Ct

    // Stage full 128x128 key|vec tile in SMEM
    float (*Ct)[132] = reinterpret_cast<float (*)[132]>(sm);
#pragma unroll
    for (int mf = 0; mf < 4; mf++) {
        int row = wm * 64 + mf * 16 + g;
#pragma unroll
        for (int nf = 0; nf < 4; nf++) {
            int col = wn * 32 + nf * 8 + 2 * t;
            Ct[row    ][col]     = acc[mf][nf][0];
            Ct[row    ][col + 1] = acc[mf][nf][1];
            Ct[row + 8][col]     = acc[mf][nf][2];
            Ct[row + 8][col + 1] = acc[mf][nf][3];
        }
    }
    __syncthreads();

    // Softmax over L per feature column. 4 threads per column, 32 rows each.
    const int j = tid >> 2;          // 0..63
    const int p = tid & 3;           // row partition
    const int h = hbase + j;
    const float qv  = g_q[(size_t)bb * NH + h];
    const float kbv = kb[h];
    const float vbv = vb[h];

    float mloc = -1e30f;
#pragma unroll 8
    for (int i = 0; i < 32; i++) {
        int l = p * 32 + i;
        float att = (Ct[l][j] + kbv) * qv;
        mloc = fmaxf(mloc, att);
    }
    mloc = fmaxf(mloc, __shfl_xor_sync(0xffffffffu, mloc, 1));
    mloc = fmaxf(mloc, __shfl_xor_sync(0xffffffffu, mloc, 2));

    float sloc = 0.0f;
#pragma unroll 8
    for (int i = 0; i < 32; i++) {
        int l = p * 32 + i;
        float att = (Ct[l][j] + kbv) * qv;
        sloc += __expf(att - mloc);
    }
    sloc += __shfl_xor_sync(0xffffffffu, sloc, 1);
    sloc += __shfl_xor_sync(0xffffffffu, sloc, 2);
    const float inv_s = 1.0f / sloc;

    float hloc = 0.0f;
#pragma unroll 8
    for (int i = 0; i < 32; i++) {
        int l = p * 32 + i;
        float att = (Ct[l][j] + kbv) * qv;
        float e = __expf(att - mloc) * inv_s;
        float val = (Ct[l][j + 64] + vbv) * e;
        hloc += lrelu(val);
    }
    hloc += __shfl_xor_sync(0xffffffffu, hloc, 1);
    hloc += __shfl_xor_sync(0xffffffffu, hloc, 2);

    if (p == 0)
        out[(size_t)bb * NH + h] = (g_xh[(size_t)bb * NH + h] + hloc) * 0.5f;
}

// ===========================================================================
// Small GEMMs (xh, q): legacy tf32 mma.sync kernel (known-good from R5).
// ===========================================================================
__device__ __forceinline__ void mma_tf32(float c[4],
                                         unsigned a0, unsigned a1, unsigned a2, unsigned a3,
                                         unsigned b0, unsigned b1) {
    asm volatile(
        "mma.sync.aligned.m16n8k8.row.col.f32.tf32.tf32.f32 "
        "{%0,%1,%2,%3}, {%4,%5,%6,%7}, {%8,%9}, {%0,%1,%2,%3};\n"
        : "+f"(c[0]), "+f"(c[1]), "+f"(c[2]), "+f"(c[3])
        : "r"(a0), "r"(a1), "r"(a2), "r"(a3), "r"(b0), "r"(b1));
}

__global__ __launch_bounds__(256) void gemm512_act(
    const float* __restrict__ A, const float* __restrict__ W,
    const float* __restrict__ bias, float* __restrict__ C, int act)
{
    __shared__ unsigned As[128][36];
    __shared__ unsigned Ws[64][36];

    const int tid  = threadIdx.x;
    const int warp = tid >> 5, lane = tid & 31;
    const int g = lane >> 2, t = lane & 3;
    const int wm = warp & 3, wn = warp >> 2;
    const int m0 = blockIdx.y * 128;
    const int n0 = blockIdx.x * 64;

    float acc[2][4][4];
#pragma unroll
    for (int mf = 0; mf < 2; mf++)
#pragma unroll
        for (int nf = 0; nf < 4; nf++)
#pragma unroll
            for (int i = 0; i < 4; i++) acc[mf][nf][i] = 0.0f;

    for (int k0 = 0; k0 < ND; k0 += 32) {
#pragma unroll
        for (int i = 0; i < 4; i++) {
            int idx = i * 256 + tid;
            int r = idx >> 3, c4 = (idx & 7) * 4;
            float4 v = *reinterpret_cast<const float4*>(&A[(size_t)(m0 + r) * ND + k0 + c4]);
            uint4 u = make_uint4(f2tf32(v.x), f2tf32(v.y), f2tf32(v.z), f2tf32(v.w));
            *reinterpret_cast<uint4*>(&As[r][c4]) = u;
        }
#pragma unroll
        for (int i = 0; i < 2; i++) {
            int idx = i * 256 + tid;
            int r = idx >> 3, c4 = (idx & 7) * 4;
            float4 v = *reinterpret_cast<const float4*>(&W[(size_t)(n0 + r) * ND + k0 + c4]);
            uint4 u = make_uint4(f2tf32(v.x), f2tf32(v.y), f2tf32(v.z), f2tf32(v.w));
            *reinterpret_cast<uint4*>(&Ws[r][c4]) = u;
        }
        __syncthreads();

#pragma unroll
        for (int ks = 0; ks < 32; ks += 8) {
            unsigned a[2][4], b[4][2];
#pragma unroll
            for (int mf = 0; mf < 2; mf++) {
                int r0 = wm * 32 + mf * 16 + g;
                a[mf][0] = As[r0    ][ks + t];
                a[mf][1] = As[r0 + 8][ks + t];
                a[mf][2] = As[r0    ][ks + t + 4];
                a[mf][3] = As[r0 + 8][ks + t + 4];
            }
#pragma unroll
            for (int nf = 0; nf < 4; nf++) {
                int c0 = wn * 32 + nf * 8 + g;
                b[nf][0] = Ws[c0][ks + t];
                b[nf][1] = Ws[c0][ks + t + 4];
            }
#pragma unroll
            for (int mf = 0; mf < 2; mf++)
#pragma unroll
                for (int nf = 0; nf < 4; nf++)
                    mma_tf32(acc[mf][nf], a[mf][0], a[mf][1], a[mf][2], a[mf][3],
                             b[nf][0], b[nf][1]);
        }
        __syncthreads();
    }

#pragma unroll
    for (int mf = 0; mf < 2; mf++) {
        int row = m0 + wm * 32 + mf * 16 + g;
#pragma unroll
        for (int nf = 0; nf < 4; nf++) {
            int col = n0 + wn * 32 + nf * 8 + 2 * t;
            float b0 = bias[col], b1 = bias[col + 1];
            float v0 = acc[mf][nf][0] + b0;
            float v1 = acc[mf][nf][1] + b1;
            float v2 = acc[mf][nf][2] + b0;
            float v3 = acc[mf][nf][3] + b1;
            if (act) { v0 = lrelu(v0); v1 = lrelu(v1); v2 = lrelu(v2); v3 = lrelu(v3); }
            *reinterpret_cast<float2*>(&C[(size_t)row * NH + col])       = make_float2(v0, v1);
            *reinterpret_cast<float2*>(&C[(size_t)(row + 8) * NH + col]) = make_float2(v2, v3);
        }
    }
}

// ===========================================================================
extern "C" void kernel_launch(void* const* d_in, const int* in_sizes, int n_in,
                              void* d_out, int out_size)
{
    (void)in_sizes; (void)n_in; (void)out_size;
    const float* x    = (const float*)d_in[0];
    const float* y    = (const float*)d_in[1];
    const float* fc_w = (const float*)d_in[2];
    const float* fc_b = (const float*)d_in[3];
    const float* q_w  = (const float*)d_in[4];
    const float* q_b  = (const float*)d_in[5];
    const float* k_w  = (const float*)d_in[6];
    const float* k_b  = (const float*)d_in[7];
    const float* v_w  = (const float*)d_in[8];
    const float* v_b  = (const float*)d_in[9];
    float* out = (float*)d_out;

    float  *p_xh, *p_q;
    __half *p_yh;
    cudaGetSymbolAddress((void**)&p_xh, g_xh);
    cudaGetSymbolAddress((void**)&p_q,  g_q);
    cudaGetSymbolAddress((void**)&p_yh, g_yh);

    const int YH_SMEM = SMEM_MAIN + 128;             // 65664
    const int AT_SMEM = 128 * 132 * 4 + 128;         // 67712 (epilogue Ct is larger)
    cudaFuncSetAttribute(yh_fp16,   cudaFuncAttributeMaxDynamicSharedMemorySize, YH_SMEM);
    cudaFuncSetAttribute(attn_fp16, cudaFuncAttributeMaxDynamicSharedMemorySize, AT_SMEM);

    // 1) xh = lrelu(x @ fc_w^T + fc_b)            [2048, 512]   (tf32)
    gemm512_act<<<dim3(8, NB / 128), 256>>>(x, fc_w, fc_b, p_xh, 1);
    // 2) q = xh @ q_w^T + q_b                     [2048, 512]   (tf32)
    gemm512_act<<<dim3(8, NB / 128), 256>>>(p_xh, q_w, q_b, p_q, 0);
    // 3) yh = lrelu(y @ fc_w^T + fc_b)            [262144, 512] (fp16 mma, half out)
    yh_fp16<<<dim3(4, (NB * NL) / 128), 256, YH_SMEM>>>(y, fc_w, fc_b, p_yh);
    // 4) key/vec GEMM (fp16 mma) + softmax epilogue -> out
    attn_fp16<<<dim3(8, NB), 256, AT_SMEM>>>(k_w, k_b, v_w, v_b, out);
}

// round 10
// speedup vs baseline: 1.7687x; 1.3874x over previous
#include <cuda_runtime.h>
#include <cuda_fp16.h>
#include <cstdint>

#define ALPHA 0.2f

// Shapes (fixed by the problem)
#define NB   2048      // batch
#define NL   128       // neighbors
#define ND   512       // IN_DIM
#define NH   512       // HID

// Scratch (device globals: allocation-free by harness rules)
__device__ __align__(16) float  g_xh[NB * NH];        // 4 MB
__device__ __align__(16) float  g_q [NB * NH];        // 4 MB
__device__ __align__(16) __half g_fc16[ND * NH];      // 512 KB  fc_w fp16
__device__ __align__(16) __half g_kw16[NH * NH];      // 512 KB  k_w fp16
__device__ __align__(16) __half g_vw16[NH * NH];      // 512 KB  v_w fp16

// ===========================================================================
// Helpers
// ===========================================================================
__device__ __forceinline__ float lrelu(float v) { return v > 0.0f ? v : ALPHA * v; }

__device__ __forceinline__ unsigned f2tf32(float x) {
    unsigned r;
    asm("cvt.rna.tf32.f32 %0, %1;" : "=r"(r) : "f"(x));
    return r;
}
__device__ __forceinline__ unsigned pack2(float a, float b) {
    __half2 h = __floats2half2_rn(a, b);
    return reinterpret_cast<unsigned&>(h);
}
__device__ __forceinline__ uint32_t smem_u32(const void* p) {
    uint32_t a;
    asm("{ .reg .u64 t; cvta.to.shared.u64 t, %1; cvt.u32.u64 %0, t; }" : "=r"(a) : "l"(p));
    return a;
}
__device__ __forceinline__ void ldmx4(uint32_t r[4], uint32_t addr) {
    asm volatile("ldmatrix.sync.aligned.m8n8.x4.shared.b16 {%0,%1,%2,%3}, [%4];"
                 : "=r"(r[0]), "=r"(r[1]), "=r"(r[2]), "=r"(r[3]) : "r"(addr));
}
__device__ __forceinline__ void mma_f16(float c[4], const uint32_t a[4],
                                        uint32_t b0, uint32_t b1) {
    asm volatile("mma.sync.aligned.m16n8k16.row.col.f32.f16.f16.f32 "
                 "{%0,%1,%2,%3}, {%4,%5,%6,%7}, {%8,%9}, {%0,%1,%2,%3};"
                 : "+f"(c[0]), "+f"(c[1]), "+f"(c[2]), "+f"(c[3])
                 : "r"(a[0]), "r"(a[1]), "r"(a[2]), "r"(a[3]), "r"(b0), "r"(b1));
}
__device__ __forceinline__ void cpa16(uint32_t dst, const void* src) {
    asm volatile("cp.async.cg.shared.global [%0], [%1], 16;" :: "r"(dst), "l"(src));
}
#define CP_COMMIT asm volatile("cp.async.commit_group;" ::: "memory")
#define CP_WAIT1  asm volatile("cp.async.wait_group 1;" ::: "memory")
#define CP_WAIT0  asm volatile("cp.async.wait_group 0;" ::: "memory")

// 16B-segment swizzle (128B rows, 8 segments): seg' = seg ^ (row & 7)
// ldmatrix address for an 8x8 fp16 tile at (rowbase, colbyte)
__device__ __forceinline__ uint32_t ldm_addr(uint32_t base, int rowbase, int colbyte, int lane) {
    int mi = lane >> 3;
    int r  = rowbase + (mi & 1) * 8 + (lane & 7);
    unsigned off = (unsigned)(r * 128 + colbyte + (mi >> 1) * 16);
    return base + (off ^ ((off >> 3) & 0x70));
}

// SMEM layout (offsets from 128B-aligned base):
//   YH tiles: 8 x [128][64] fp16 swizzled, tile k at k*16384      [0, 131072)
//   B bufs (x3): 131072 + i*16384                                 [131072, 180224)
//   A bufs (x3): 180224 + i*16384 (phase 1 only)                  [180224, 229376)
//   Ct epilogue float[128][132] aliases [131072, 198656)  (phase 2 only)
#define YH_OFF(k)  ((k) * 16384)
#define B_OFF(i)   (131072 + (i) * 16384)
#define A_OFF(i)   (180224 + (i) * 16384)
#define CT_OFF     131072
#define SMEM_FUSED (229376 + 128)

// ===========================================================================
// Weight pre-convert: fc_w / k_w / v_w f32 -> fp16
// ===========================================================================
__global__ void wcvt(const float* __restrict__ fc, const float* __restrict__ kw,
                     const float* __restrict__ vw) {
    int i = blockIdx.x * blockDim.x + threadIdx.x;     // 0..65535, 4 floats each
    float4 a = *reinterpret_cast<const float4*>(fc + (size_t)i * 4);
    float4 b = *reinterpret_cast<const float4*>(kw + (size_t)i * 4);
    float4 c = *reinterpret_cast<const float4*>(vw + (size_t)i * 4);
    uint2 ua = make_uint2(pack2(a.x, a.y), pack2(a.z, a.w));
    uint2 ub = make_uint2(pack2(b.x, b.y), pack2(b.z, b.w));
    uint2 uc = make_uint2(pack2(c.x, c.y), pack2(c.z, c.w));
    *reinterpret_cast<uint2*>(&g_fc16[(size_t)i * 4]) = ua;
    *reinterpret_cast<uint2*>(&g_kw16[(size_t)i * 4]) = ub;
    *reinterpret_cast<uint2*>(&g_vw16[(size_t)i * 4]) = uc;
}

// ===========================================================================
// Fused per-batch kernel:
//   Phase 1: yh_b = lrelu(y_b @ fc_w^T + fc_b) -> SMEM fp16 (swizzled tiles)
//   Phase 2: 8x { key|vec chunk GEMM from SMEM yh + softmax-over-L epilogue }
// ===========================================================================
__global__ __launch_bounds__(256) void fused(
    const float* __restrict__ y, const float* __restrict__ fc_b,
    const float* __restrict__ kb, const float* __restrict__ vb,
    float* __restrict__ out)
{
    extern __shared__ char smem_raw[];
    char* sm = smem_raw + ((128 - ((uintptr_t)smem_raw & 127)) & 127);
    const uint32_t sb = smem_u32(sm);

    const int tid = threadIdx.x, warp = tid >> 5, lane = tid & 31;
    const int g = lane >> 2, t = lane & 3;
    const int wm = warp & 1, wn = warp >> 1;            // 2 x 4 warp grid
    const int bb = blockIdx.x;
    const float* yb = y + (size_t)bb * NL * ND;

    float acc[4][4][4];
    uint4 ra[4];

    auto zacc = [&] {
#pragma unroll
        for (int mf = 0; mf < 4; mf++)
#pragma unroll
            for (int nf = 0; nf < 4; nf++)
#pragma unroll
                for (int i = 0; i < 4; i++) acc[mf][nf][i] = 0.0f;
    };

    // Phase-1 A: y f32 -> fp16 into registers
    auto ldgA = [&](int c) {
#pragma unroll
        for (int i = 0; i < 4; i++) {
            int idx = i * 256 + tid;
            int r = idx >> 3, s = idx & 7;
            const float* p = yb + (size_t)r * ND + c * 64 + s * 8;
            float4 a0 = *reinterpret_cast<const float4*>(p);
            float4 a1 = *reinterpret_cast<const float4*>(p + 4);
            ra[i] = make_uint4(pack2(a0.x, a0.y), pack2(a0.z, a0.w),
                               pack2(a1.x, a1.y), pack2(a1.z, a1.w));
        }
    };
    auto stsA = [&](int buf) {
#pragma unroll
        for (int i = 0; i < 4; i++) {
            int idx = i * 256 + tid;
            int r = idx >> 3, s = idx & 7;
            unsigned off = (unsigned)(r * 128 + ((s ^ (r & 7)) * 16));
            *reinterpret_cast<uint4*>(sm + A_OFF(buf) + off) = ra[i];
        }
    };
    // Phase-1 B: fc16 rows [nt*128, +128) via cp.async
    auto cpB1 = [&](int buf, int c, int nt) {
#pragma unroll
        for (int i = 0; i < 4; i++) {
            int idx = i * 256 + tid;
            int r = idx >> 3, s = idx & 7;
            const __half* src = g_fc16 + (size_t)(nt * 128 + r) * NH + c * 64 + s * 8;
            unsigned off = (unsigned)(r * 128 + ((s ^ (r & 7)) * 16));
            cpa16(sb + B_OFF(buf) + off, src);
        }
    };
    // Phase-2 B: rows 0..63 = kw16[hbase+r], 64..127 = vw16[hbase+r-64]
    auto cpB2 = [&](int buf, int c, int ht) {
#pragma unroll
        for (int i = 0; i < 4; i++) {
            int idx = i * 256 + tid;
            int r = idx >> 3, s = idx & 7;
            const __half* src = (r < 64)
                ? (g_kw16 + (size_t)(ht * 64 + r) * NH + c * 64 + s * 8)
                : (g_vw16 + (size_t)(ht * 64 + r - 64) * NH + c * 64 + s * 8);
            unsigned off = (unsigned)(r * 128 + ((s ^ (r & 7)) * 16));
            cpa16(sb + B_OFF(buf) + off, src);
        }
    };
    auto mmac = [&](uint32_t Abase, uint32_t Bbase) {
#pragma unroll
        for (int ks = 0; ks < 4; ks++) {
            uint32_t a[4][4], b[2][4];
#pragma unroll
            for (int mf = 0; mf < 4; mf++)
                ldmx4(a[mf], ldm_addr(Abase, wm * 64 + mf * 16, ks * 32, lane));
#pragma unroll
            for (int np = 0; np < 2; np++)
                ldmx4(b[np], ldm_addr(Bbase, wn * 32 + np * 16, ks * 32, lane));
#pragma unroll
            for (int mf = 0; mf < 4; mf++)
#pragma unroll
                for (int nf = 0; nf < 4; nf++)
                    mma_f16(acc[mf][nf], a[mf], b[nf >> 1][nf & 1], b[nf >> 1][(nf & 1) + 2]);
        }
    };

    // ---------------- Phase 1: yh_b -> SMEM ----------------
    for (int nt = 0; nt < 4; nt++) {
        zacc();
        ldgA(0); stsA(0); cpB1(0, 0, nt); CP_COMMIT;
        ldgA(1); stsA(1); cpB1(1, 1, nt); CP_COMMIT;
        ldgA(2);
        for (int c = 0; c < 8; c++) {
            if (c < 7) { CP_WAIT1; } else { CP_WAIT0; }
            __syncthreads();
            if (c + 2 < 8) { stsA((c + 2) % 3); cpB1((c + 2) % 3, c + 2, nt); CP_COMMIT; }
            if (c + 3 < 8) ldgA(c + 3);
            mmac(sb + A_OFF(c % 3), sb + B_OFF(c % 3));
        }
        // epilogue: bias + lrelu -> fp16 into YH tiles (swizzled)
#pragma unroll
        for (int mf = 0; mf < 4; mf++) {
            int row = wm * 64 + mf * 16 + g;
#pragma unroll
            for (int nf = 0; nf < 4; nf++) {
                int colg = nt * 128 + wn * 32 + nf * 8 + 2 * t;
                int tile = colg >> 6, cc = colg & 63;
                float b0 = fc_b[colg], b1 = fc_b[colg + 1];
                __half2 h0 = __floats2half2_rn(lrelu(acc[mf][nf][0] + b0),
                                               lrelu(acc[mf][nf][1] + b1));
                __half2 h1 = __floats2half2_rn(lrelu(acc[mf][nf][2] + b0),
                                               lrelu(acc[mf][nf][3] + b1));
                unsigned o0 = (unsigned)(row * 128 + cc * 2);
                o0 ^= (o0 >> 3) & 0x70;
                *reinterpret_cast<__half2*>(sm + YH_OFF(tile) + o0) = h0;
                unsigned o1 = (unsigned)((row + 8) * 128 + cc * 2);
                o1 ^= (o1 >> 3) & 0x70;
                *reinterpret_cast<__half2*>(sm + YH_OFF(tile) + o1) = h1;
            }
        }
        __syncthreads();
    }

    // ---------------- Phase 2: key|vec chunks + softmax ----------------
    for (int ht = 0; ht < 8; ht++) {
        zacc();
        cpB2(0, 0, ht); CP_COMMIT;
        cpB2(1, 1, ht); CP_COMMIT;
        for (int c = 0; c < 8; c++) {
            if (c < 7) { CP_WAIT1; } else { CP_WAIT0; }
            __syncthreads();
            if (c + 2 < 8) { cpB2((c + 2) % 3, c + 2, ht); CP_COMMIT; }
            mmac(sb + YH_OFF(c), sb + B_OFF(c % 3));
        }
        __syncthreads();   // all B-buf reads done; Ct aliases them

        // Stage the 128x128 key|vec tile in SMEM
        float (*Ct)[132] = reinterpret_cast<float (*)[132]>(sm + CT_OFF);
#pragma unroll
        for (int mf = 0; mf < 4; mf++) {
            int row = wm * 64 + mf * 16 + g;
#pragma unroll
            for (int nf = 0; nf < 4; nf++) {
                int col = wn * 32 + nf * 8 + 2 * t;
                Ct[row    ][col]     = acc[mf][nf][0];
                Ct[row    ][col + 1] = acc[mf][nf][1];
                Ct[row + 8][col]     = acc[mf][nf][2];
                Ct[row + 8][col + 1] = acc[mf][nf][3];
            }
        }
        __syncthreads();

        // Softmax over L per feature column. 4 threads per column, 32 rows each.
        const int j = tid >> 2;          // 0..63
        const int p = tid & 3;           // row partition
        const int h = ht * 64 + j;
        const float qv  = g_q[(size_t)bb * NH + h];
        const float kbv = kb[h];
        const float vbv = vb[h];

        float mloc = -1e30f;
#pragma unroll 8
        for (int i = 0; i < 32; i++) {
            int l = p * 32 + i;
            float att = (Ct[l][j] + kbv) * qv;
            mloc = fmaxf(mloc, att);
        }
        mloc = fmaxf(mloc, __shfl_xor_sync(0xffffffffu, mloc, 1));
        mloc = fmaxf(mloc, __shfl_xor_sync(0xffffffffu, mloc, 2));

        float sloc = 0.0f;
#pragma unroll 8
        for (int i = 0; i < 32; i++) {
            int l = p * 32 + i;
            float att = (Ct[l][j] + kbv) * qv;
            sloc += __expf(att - mloc);
        }
        sloc += __shfl_xor_sync(0xffffffffu, sloc, 1);
        sloc += __shfl_xor_sync(0xffffffffu, sloc, 2);
        const float inv_s = 1.0f / sloc;

        float hloc = 0.0f;
#pragma unroll 8
        for (int i = 0; i < 32; i++) {
            int l = p * 32 + i;
            float att = (Ct[l][j] + kbv) * qv;
            float e = __expf(att - mloc) * inv_s;
            float val = (Ct[l][j + 64] + vbv) * e;
            hloc += lrelu(val);
        }
        hloc += __shfl_xor_sync(0xffffffffu, hloc, 1);
        hloc += __shfl_xor_sync(0xffffffffu, hloc, 2);

        if (p == 0)
            out[(size_t)bb * NH + h] = (g_xh[(size_t)bb * NH + h] + hloc) * 0.5f;

        __syncthreads();   // Ct reads done before next ht's cp.async prologue
    }
}

// ===========================================================================
// Small GEMMs (xh, q): legacy tf32 mma.sync kernel (known-good).
// ===========================================================================
__device__ __forceinline__ void mma_tf32(float c[4],
                                         unsigned a0, unsigned a1, unsigned a2, unsigned a3,
                                         unsigned b0, unsigned b1) {
    asm volatile(
        "mma.sync.aligned.m16n8k8.row.col.f32.tf32.tf32.f32 "
        "{%0,%1,%2,%3}, {%4,%5,%6,%7}, {%8,%9}, {%0,%1,%2,%3};\n"
        : "+f"(c[0]), "+f"(c[1]), "+f"(c[2]), "+f"(c[3])
        : "r"(a0), "r"(a1), "r"(a2), "r"(a3), "r"(b0), "r"(b1));
}

__global__ __launch_bounds__(256) void gemm512_act(
    const float* __restrict__ A, const float* __restrict__ W,
    const float* __restrict__ bias, float* __restrict__ C, int act)
{
    __shared__ unsigned As[128][36];
    __shared__ unsigned Ws[64][36];

    const int tid  = threadIdx.x;
    const int warp = tid >> 5, lane = tid & 31;
    const int g = lane >> 2, t = lane & 3;
    const int wm = warp & 3, wn = warp >> 2;
    const int m0 = blockIdx.y * 128;
    const int n0 = blockIdx.x * 64;

    float acc[2][4][4];
#pragma unroll
    for (int mf = 0; mf < 2; mf++)
#pragma unroll
        for (int nf = 0; nf < 4; nf++)
#pragma unroll
            for (int i = 0; i < 4; i++) acc[mf][nf][i] = 0.0f;

    for (int k0 = 0; k0 < ND; k0 += 32) {
#pragma unroll
        for (int i = 0; i < 4; i++) {
            int idx = i * 256 + tid;
            int r = idx >> 3, c4 = (idx & 7) * 4;
            float4 v = *reinterpret_cast<const float4*>(&A[(size_t)(m0 + r) * ND + k0 + c4]);
            uint4 u = make_uint4(f2tf32(v.x), f2tf32(v.y), f2tf32(v.z), f2tf32(v.w));
            *reinterpret_cast<uint4*>(&As[r][c4]) = u;
        }
#pragma unroll
        for (int i = 0; i < 2; i++) {
            int idx = i * 256 + tid;
            int r = idx >> 3, c4 = (idx & 7) * 4;
            float4 v = *reinterpret_cast<const float4*>(&W[(size_t)(n0 + r) * ND + k0 + c4]);
            uint4 u = make_uint4(f2tf32(v.x), f2tf32(v.y), f2tf32(v.z), f2tf32(v.w));
            *reinterpret_cast<uint4*>(&Ws[r][c4]) = u;
        }
        __syncthreads();

#pragma unroll
        for (int ks = 0; ks < 32; ks += 8) {
            unsigned a[2][4], b[4][2];
#pragma unroll
            for (int mf = 0; mf < 2; mf++) {
                int r0 = wm * 32 + mf * 16 + g;
                a[mf][0] = As[r0    ][ks + t];
                a[mf][1] = As[r0 + 8][ks + t];
                a[mf][2] = As[r0    ][ks + t + 4];
                a[mf][3] = As[r0 + 8][ks + t + 4];
            }
#pragma unroll
            for (int nf = 0; nf < 4; nf++) {
                int c0 = wn * 32 + nf * 8 + g;
                b[nf][0] = Ws[c0][ks + t];
                b[nf][1] = Ws[c0][ks + t + 4];
            }
#pragma unroll
            for (int mf = 0; mf < 2; mf++)
#pragma unroll
                for (int nf = 0; nf < 4; nf++)
                    mma_tf32(acc[mf][nf], a[mf][0], a[mf][1], a[mf][2], a[mf][3],
                             b[nf][0], b[nf][1]);
        }
        __syncthreads();
    }

#pragma unroll
    for (int mf = 0; mf < 2; mf++) {
        int row = m0 + wm * 32 + mf * 16 + g;
#pragma unroll
        for (int nf = 0; nf < 4; nf++) {
            int col = n0 + wn * 32 + nf * 8 + 2 * t;
            float b0 = bias[col], b1 = bias[col + 1];
            float v0 = acc[mf][nf][0] + b0;
            float v1 = acc[mf][nf][1] + b1;
            float v2 = acc[mf][nf][2] + b0;
            float v3 = acc[mf][nf][3] + b1;
            if (act) { v0 = lrelu(v0); v1 = lrelu(v1); v2 = lrelu(v2); v3 = lrelu(v3); }
            *reinterpret_cast<float2*>(&C[(size_t)row * NH + col])       = make_float2(v0, v1);
            *reinterpret_cast<float2*>(&C[(size_t)(row + 8) * NH + col]) = make_float2(v2, v3);
        }
    }
}

// ===========================================================================
extern "C" void kernel_launch(void* const* d_in, const int* in_sizes, int n_in,
                              void* d_out, int out_size)
{
    (void)in_sizes; (void)n_in; (void)out_size;
    const float* x    = (const float*)d_in[0];
    const float* y    = (const float*)d_in[1];
    const float* fc_w = (const float*)d_in[2];
    const float* fc_b = (const float*)d_in[3];
    const float* q_w  = (const float*)d_in[4];
    const float* q_b  = (const float*)d_in[5];
    const float* k_w  = (const float*)d_in[6];
    const float* k_b  = (const float*)d_in[7];
    const float* v_w  = (const float*)d_in[8];
    const float* v_b  = (const float*)d_in[9];
    float* out = (float*)d_out;

    float *p_xh, *p_q;
    cudaGetSymbolAddress((void**)&p_xh, g_xh);
    cudaGetSymbolAddress((void**)&p_q,  g_q);

    cudaFuncSetAttribute(fused, cudaFuncAttributeMaxDynamicSharedMemorySize, SMEM_FUSED);

    // 0) weights f32 -> fp16                        (~6 MB traffic)
    wcvt<<<256, 256>>>(fc_w, k_w, v_w);
    // 1) xh = lrelu(x @ fc_w^T + fc_b)              [2048, 512]  (tf32)
    gemm512_act<<<dim3(8, NB / 128), 256>>>(x, fc_w, fc_b, p_xh, 1);
    // 2) q = xh @ q_w^T + q_b                       [2048, 512]  (tf32)
    gemm512_act<<<dim3(8, NB / 128), 256>>>(p_xh, q_w, q_b, p_q, 0);
    // 3) fused per-batch: yh (SMEM-resident) + key/vec GEMM + softmax -> out
    fused<<<NB, 256, SMEM_FUSED>>>(y, fc_b, k_b, v_b, out);
}

// round 11
// speedup vs baseline: 1.9572x; 1.1066x over previous
#include <cuda_runtime.h>
#include <cuda_fp16.h>
#include <cstdint>

#define ALPHA 0.2f

// Shapes (fixed by the problem)
#define NB   2048      // batch
#define NL   128       // neighbors
#define ND   512       // IN_DIM
#define NH   512       // HID

// Scratch (device globals: allocation-free by harness rules)
__device__ __align__(16) float  g_xh[NB * NH];        // 4 MB
__device__ __align__(16) float  g_q [NB * NH];        // 4 MB
__device__ __align__(16) __half g_fc16[ND * NH];      // 512 KB  fc_w fp16
__device__ __align__(16) __half g_kw16[NH * NH];      // 512 KB  k_w fp16
__device__ __align__(16) __half g_vw16[NH * NH];      // 512 KB  v_w fp16

// ===========================================================================
// Helpers
// ===========================================================================
__device__ __forceinline__ float lrelu(float v) { return v > 0.0f ? v : ALPHA * v; }

__device__ __forceinline__ unsigned f2tf32(float x) {
    unsigned r;
    asm("cvt.rna.tf32.f32 %0, %1;" : "=r"(r) : "f"(x));
    return r;
}
__device__ __forceinline__ unsigned pack2(float a, float b) {
    __half2 h = __floats2half2_rn(a, b);
    return reinterpret_cast<unsigned&>(h);
}
__device__ __forceinline__ uint32_t smem_u32(const void* p) {
    uint32_t a;
    asm("{ .reg .u64 t; cvta.to.shared.u64 t, %1; cvt.u32.u64 %0, t; }" : "=r"(a) : "l"(p));
    return a;
}
__device__ __forceinline__ void ldmx4(uint32_t r[4], uint32_t addr) {
    asm volatile("ldmatrix.sync.aligned.m8n8.x4.shared.b16 {%0,%1,%2,%3}, [%4];"
                 : "=r"(r[0]), "=r"(r[1]), "=r"(r[2]), "=r"(r[3]) : "r"(addr));
}
__device__ __forceinline__ void mma_f16(float c[4], const uint32_t a[4],
                                        uint32_t b0, uint32_t b1) {
    asm volatile("mma.sync.aligned.m16n8k16.row.col.f32.f16.f16.f32 "
                 "{%0,%1,%2,%3}, {%4,%5,%6,%7}, {%8,%9}, {%0,%1,%2,%3};"
                 : "+f"(c[0]), "+f"(c[1]), "+f"(c[2]), "+f"(c[3])
                 : "r"(a[0]), "r"(a[1]), "r"(a[2]), "r"(a[3]), "r"(b0), "r"(b1));
}
__device__ __forceinline__ void cpa16(uint32_t dst, const void* src) {
    asm volatile("cp.async.cg.shared.global [%0], [%1], 16;" :: "r"(dst), "l"(src));
}
#define CP_COMMIT asm volatile("cp.async.commit_group;" ::: "memory")
#define CP_WAIT1  asm volatile("cp.async.wait_group 1;" ::: "memory")
#define CP_WAIT0  asm volatile("cp.async.wait_group 0;" ::: "memory")

// 16B-segment swizzle (128B rows, 8 segments): seg' = seg ^ (row & 7)
// ldmatrix address for an 8x8 fp16 tile at (rowbase, colbyte)
__device__ __forceinline__ uint32_t ldm_addr(uint32_t base, int rowbase, int colbyte, int lane) {
    int mi = lane >> 3;
    int r  = rowbase + (mi & 1) * 8 + (lane & 7);
    unsigned off = (unsigned)(r * 128 + colbyte + (mi >> 1) * 16);
    return base + (off ^ ((off >> 3) & 0x70));
}

// SMEM layout (offsets from 128B-aligned base):
//   YH tiles: 8 x [128][64] fp16 swizzled, tile k at k*16384      [0, 131072)
//   B bufs (x3): 131072 + i*16384                                 [131072, 180224)
//   A bufs (x3): 180224 + i*16384 (phase 1 only)                  [180224, 229376)
//   sred (phase-2 softmax scratch, 1.5 KB) aliases A buf 0.
#define YH_OFF(k)  ((k) * 16384)
#define B_OFF(i)   (131072 + (i) * 16384)
#define A_OFF(i)   (180224 + (i) * 16384)
#define SMEM_FUSED (229376 + 128)

// ===========================================================================
// Weight pre-convert: fc_w / k_w / v_w f32 -> fp16
// ===========================================================================
__global__ void wcvt(const float* __restrict__ fc, const float* __restrict__ kw,
                     const float* __restrict__ vw) {
    int i = blockIdx.x * blockDim.x + threadIdx.x;     // 0..65535, 4 floats each
    float4 a = *reinterpret_cast<const float4*>(fc + (size_t)i * 4);
    float4 b = *reinterpret_cast<const float4*>(kw + (size_t)i * 4);
    float4 c = *reinterpret_cast<const float4*>(vw + (size_t)i * 4);
    uint2 ua = make_uint2(pack2(a.x, a.y), pack2(a.z, a.w));
    uint2 ub = make_uint2(pack2(b.x, b.y), pack2(b.z, b.w));
    uint2 uc = make_uint2(pack2(c.x, c.y), pack2(c.z, c.w));
    *reinterpret_cast<uint2*>(&g_fc16[(size_t)i * 4]) = ua;
    *reinterpret_cast<uint2*>(&g_kw16[(size_t)i * 4]) = ub;
    *reinterpret_cast<uint2*>(&g_vw16[(size_t)i * 4]) = uc;
}

// ===========================================================================
// Fused per-batch kernel:
//   Phase 1: yh_b = lrelu(y_b @ fc_w^T + fc_b) -> SMEM fp16 (swizzled tiles)
//   Phase 2: 8x { key|vec chunk GEMM (kv-interleaved B) + register softmax }
// ===========================================================================
__global__ __launch_bounds__(256) void fused(
    const float* __restrict__ y, const float* __restrict__ fc_b,
    const float* __restrict__ kb, const float* __restrict__ vb,
    float* __restrict__ out)
{
    extern __shared__ char smem_raw[];
    char* sm = smem_raw + ((128 - ((uintptr_t)smem_raw & 127)) & 127);
    const uint32_t sb = smem_u32(sm);

    const int tid = threadIdx.x, warp = tid >> 5, lane = tid & 31;
    const int g = lane >> 2, t = lane & 3;
    const int wm = warp & 1, wn = warp >> 1;            // 2 x 4 warp grid
    const int bb = blockIdx.x;
    const float* yb = y + (size_t)bb * NL * ND;

    float acc[4][4][4];
    uint4 ra[4];

    auto zacc = [&] {
#pragma unroll
        for (int mf = 0; mf < 4; mf++)
#pragma unroll
            for (int nf = 0; nf < 4; nf++)
#pragma unroll
                for (int i = 0; i < 4; i++) acc[mf][nf][i] = 0.0f;
    };

    // Phase-1 A: y f32 -> fp16 into registers
    auto ldgA = [&](int c) {
#pragma unroll
        for (int i = 0; i < 4; i++) {
            int idx = i * 256 + tid;
            int r = idx >> 3, s = idx & 7;
            const float* p = yb + (size_t)r * ND + c * 64 + s * 8;
            float4 a0 = *reinterpret_cast<const float4*>(p);
            float4 a1 = *reinterpret_cast<const float4*>(p + 4);
            ra[i] = make_uint4(pack2(a0.x, a0.y), pack2(a0.z, a0.w),
                               pack2(a1.x, a1.y), pack2(a1.z, a1.w));
        }
    };
    auto stsA = [&](int buf) {
#pragma unroll
        for (int i = 0; i < 4; i++) {
            int idx = i * 256 + tid;
            int r = idx >> 3, s = idx & 7;
            unsigned off = (unsigned)(r * 128 + ((s ^ (r & 7)) * 16));
            *reinterpret_cast<uint4*>(sm + A_OFF(buf) + off) = ra[i];
        }
    };
    // Phase-1 B: fc16 rows [nt*128, +128) via cp.async
    auto cpB1 = [&](int buf, int c, int nt) {
#pragma unroll
        for (int i = 0; i < 4; i++) {
            int idx = i * 256 + tid;
            int r = idx >> 3, s = idx & 7;
            const __half* src = g_fc16 + (size_t)(nt * 128 + r) * NH + c * 64 + s * 8;
            unsigned off = (unsigned)(r * 128 + ((s ^ (r & 7)) * 16));
            cpa16(sb + B_OFF(buf) + off, src);
        }
    };
    // Phase-2 B (kv-interleaved): row 2j = k_w[ht*64+j], row 2j+1 = v_w[ht*64+j]
    auto cpB2 = [&](int buf, int c, int ht) {
#pragma unroll
        for (int i = 0; i < 4; i++) {
            int idx = i * 256 + tid;
            int r = idx >> 3, s = idx & 7;
            int f = ht * 64 + (r >> 1);
            const __half* base = (r & 1) ? g_vw16 : g_kw16;
            const __half* src = base + (size_t)f * NH + c * 64 + s * 8;
            unsigned off = (unsigned)(r * 128 + ((s ^ (r & 7)) * 16));
            cpa16(sb + B_OFF(buf) + off, src);
        }
    };
    auto mmac = [&](uint32_t Abase, uint32_t Bbase) {
#pragma unroll
        for (int ks = 0; ks < 4; ks++) {
            uint32_t a[4][4], b[2][4];
#pragma unroll
            for (int mf = 0; mf < 4; mf++)
                ldmx4(a[mf], ldm_addr(Abase, wm * 64 + mf * 16, ks * 32, lane));
#pragma unroll
            for (int np = 0; np < 2; np++)
                ldmx4(b[np], ldm_addr(Bbase, wn * 32 + np * 16, ks * 32, lane));
#pragma unroll
            for (int mf = 0; mf < 4; mf++)
#pragma unroll
                for (int nf = 0; nf < 4; nf++)
                    mma_f16(acc[mf][nf], a[mf], b[nf >> 1][nf & 1], b[nf >> 1][(nf & 1) + 2]);
        }
    };

    // ---------------- Phase 1: yh_b -> SMEM ----------------
    for (int nt = 0; nt < 4; nt++) {
        zacc();
        ldgA(0); stsA(0); cpB1(0, 0, nt); CP_COMMIT;
        ldgA(1); stsA(1); cpB1(1, 1, nt); CP_COMMIT;
        ldgA(2);
        for (int c = 0; c < 8; c++) {
            if (c < 7) { CP_WAIT1; } else { CP_WAIT0; }
            __syncthreads();
            if (c + 2 < 8) { stsA((c + 2) % 3); cpB1((c + 2) % 3, c + 2, nt); CP_COMMIT; }
            if (c + 3 < 8) ldgA(c + 3);
            mmac(sb + A_OFF(c % 3), sb + B_OFF(c % 3));
        }
        // epilogue: bias + lrelu -> fp16 into YH tiles (swizzled)
#pragma unroll
        for (int mf = 0; mf < 4; mf++) {
            int row = wm * 64 + mf * 16 + g;
#pragma unroll
            for (int nf = 0; nf < 4; nf++) {
                int colg = nt * 128 + wn * 32 + nf * 8 + 2 * t;
                int tile = colg >> 6, cc = colg & 63;
                float b0 = fc_b[colg], b1 = fc_b[colg + 1];
                __half2 h0 = __floats2half2_rn(lrelu(acc[mf][nf][0] + b0),
                                               lrelu(acc[mf][nf][1] + b1));
                __half2 h1 = __floats2half2_rn(lrelu(acc[mf][nf][2] + b0),
                                               lrelu(acc[mf][nf][3] + b1));
                unsigned o0 = (unsigned)(row * 128 + cc * 2);
                o0 ^= (o0 >> 3) & 0x70;
                *reinterpret_cast<__half2*>(sm + YH_OFF(tile) + o0) = h0;
                unsigned o1 = (unsigned)((row + 8) * 128 + cc * 2);
                o1 ^= (o1 >> 3) & 0x70;
                *reinterpret_cast<__half2*>(sm + YH_OFF(tile) + o1) = h1;
            }
        }
        __syncthreads();
    }

    // ---------------- Phase 2: kv chunks + register softmax ----------------
    // sred aliases A buf 0 (A bufs unused in phase 2).
    float* sred  = reinterpret_cast<float*>(sm + A_OFF(0));          // [2][64] max
    float* sred2 = reinterpret_cast<float*>(sm + A_OFF(0) + 512);    // [2][64][2] z,h

    for (int ht = 0; ht < 8; ht++) {
        zacc();
        cpB2(0, 0, ht); CP_COMMIT;
        cpB2(1, 1, ht); CP_COMMIT;
        for (int c = 0; c < 8; c++) {
            if (c < 7) { CP_WAIT1; } else { CP_WAIT0; }
            __syncthreads();
            if (c + 2 < 8) { cpB2((c + 2) % 3, c + 2, ht); CP_COMMIT; }
            mmac(sb + YH_OFF(c), sb + B_OFF(c % 3));
        }

        // Register epilogue. Fragment: c[0]=key(row), c[1]=vec(row),
        // c[2]=key(row+8), c[3]=vec(row+8); feature = wn*16 + nf*4 + t.
        float qv[4], kbv[4], vbv[4];
#pragma unroll
        for (int nf = 0; nf < 4; nf++) {
            int h = ht * 64 + wn * 16 + nf * 4 + t;
            qv[nf]  = g_q[(size_t)bb * NH + h];
            kbv[nf] = kb[h];
            vbv[nf] = vb[h];
        }

        // Pass 1: max over L (regs -> lanes -> cross-warp)
        float mx[4];
#pragma unroll
        for (int nf = 0; nf < 4; nf++) {
            float m = -1e30f;
#pragma unroll
            for (int mf = 0; mf < 4; mf++) {
                m = fmaxf(m, (acc[mf][nf][0] + kbv[nf]) * qv[nf]);
                m = fmaxf(m, (acc[mf][nf][2] + kbv[nf]) * qv[nf]);
            }
            m = fmaxf(m, __shfl_xor_sync(0xffffffffu, m, 4));
            m = fmaxf(m, __shfl_xor_sync(0xffffffffu, m, 8));
            m = fmaxf(m, __shfl_xor_sync(0xffffffffu, m, 16));
            mx[nf] = m;
        }
        if (g == 0) {
#pragma unroll
            for (int nf = 0; nf < 4; nf++)
                sred[wm * 64 + wn * 16 + nf * 4 + t] = mx[nf];
        }
        __syncthreads();

        // Pass 2: Z and h partial sums (lrelu is positively homogeneous:
        // sum lrelu(vec*e) = (1/Z) * sum lrelu(vec*exp(att-m)))
        float zp[4], hp[4];
#pragma unroll
        for (int nf = 0; nf < 4; nf++) {
            int f = wn * 16 + nf * 4 + t;
            float m = fmaxf(sred[f], sred[64 + f]);
            float z = 0.0f, hs = 0.0f;
#pragma unroll
            for (int mf = 0; mf < 4; mf++) {
                float e0 = __expf((acc[mf][nf][0] + kbv[nf]) * qv[nf] - m);
                z += e0;
                hs += lrelu((acc[mf][nf][1] + vbv[nf]) * e0);
                float e1 = __expf((acc[mf][nf][2] + kbv[nf]) * qv[nf] - m);
                z += e1;
                hs += lrelu((acc[mf][nf][3] + vbv[nf]) * e1);
            }
            z  += __shfl_xor_sync(0xffffffffu, z, 4);
            z  += __shfl_xor_sync(0xffffffffu, z, 8);
            z  += __shfl_xor_sync(0xffffffffu, z, 16);
            hs += __shfl_xor_sync(0xffffffffu, hs, 4);
            hs += __shfl_xor_sync(0xffffffffu, hs, 8);
            hs += __shfl_xor_sync(0xffffffffu, hs, 16);
            zp[nf] = z; hp[nf] = hs;
        }
        if (g == 0) {
#pragma unroll
            for (int nf = 0; nf < 4; nf++) {
                int f = wn * 16 + nf * 4 + t;
                sred2[(wm * 64 + f) * 2]     = zp[nf];
                sred2[(wm * 64 + f) * 2 + 1] = hp[nf];
            }
        }
        __syncthreads();

        if (wm == 0 && g == 0) {
#pragma unroll
            for (int nf = 0; nf < 4; nf++) {
                int f = wn * 16 + nf * 4 + t;
                float z  = sred2[f * 2]     + sred2[(64 + f) * 2];
                float hs = sred2[f * 2 + 1] + sred2[(64 + f) * 2 + 1];
                int h = ht * 64 + f;
                out[(size_t)bb * NH + h] =
                    (g_xh[(size_t)bb * NH + h] + hs / z) * 0.5f;
            }
        }
        // No extra sync: next ht's first mainloop barrier orders sred reuse.
    }
}

// ===========================================================================
// Small GEMMs (xh, q): legacy tf32 mma.sync kernel (known-good).
// ===========================================================================
__device__ __forceinline__ void mma_tf32(float c[4],
                                         unsigned a0, unsigned a1, unsigned a2, unsigned a3,
                                         unsigned b0, unsigned b1) {
    asm volatile(
        "mma.sync.aligned.m16n8k8.row.col.f32.tf32.tf32.f32 "
        "{%0,%1,%2,%3}, {%4,%5,%6,%7}, {%8,%9}, {%0,%1,%2,%3};\n"
        : "+f"(c[0]), "+f"(c[1]), "+f"(c[2]), "+f"(c[3])
        : "r"(a0), "r"(a1), "r"(a2), "r"(a3), "r"(b0), "r"(b1));
}

__global__ __launch_bounds__(256) void gemm512_act(
    const float* __restrict__ A, const float* __restrict__ W,
    const float* __restrict__ bias, float* __restrict__ C, int act)
{
    __shared__ unsigned As[128][36];
    __shared__ unsigned Ws[64][36];

    const int tid  = threadIdx.x;
    const int warp = tid >> 5, lane = tid & 31;
    const int g = lane >> 2, t = lane & 3;
    const int wm = warp & 3, wn = warp >> 2;
    const int m0 = blockIdx.y * 128;
    const int n0 = blockIdx.x * 64;

    float acc[2][4][4];
#pragma unroll
    for (int mf = 0; mf < 2; mf++)
#pragma unroll
        for (int nf = 0; nf < 4; nf++)
#pragma unroll
            for (int i = 0; i < 4; i++) acc[mf][nf][i] = 0.0f;

    for (int k0 = 0; k0 < ND; k0 += 32) {
#pragma unroll
        for (int i = 0; i < 4; i++) {
            int idx = i * 256 + tid;
            int r = idx >> 3, c4 = (idx & 7) * 4;
            float4 v = *reinterpret_cast<const float4*>(&A[(size_t)(m0 + r) * ND + k0 + c4]);
            uint4 u = make_uint4(f2tf32(v.x), f2tf32(v.y), f2tf32(v.z), f2tf32(v.w));
            *reinterpret_cast<uint4*>(&As[r][c4]) = u;
        }
#pragma unroll
        for (int i = 0; i < 2; i++) {
            int idx = i * 256 + tid;
            int r = idx >> 3, c4 = (idx & 7) * 4;
            float4 v = *reinterpret_cast<const float4*>(&W[(size_t)(n0 + r) * ND + k0 + c4]);
            uint4 u = make_uint4(f2tf32(v.x), f2tf32(v.y), f2tf32(v.z), f2tf32(v.w));
            *reinterpret_cast<uint4*>(&Ws[r][c4]) = u;
        }
        __syncthreads();

#pragma unroll
        for (int ks = 0; ks < 32; ks += 8) {
            unsigned a[2][4], b[4][2];
#pragma unroll
            for (int mf = 0; mf < 2; mf++) {
                int r0 = wm * 32 + mf * 16 + g;
                a[mf][0] = As[r0    ][ks + t];
                a[mf][1] = As[r0 + 8][ks + t];
                a[mf][2] = As[r0    ][ks + t + 4];
                a[mf][3] = As[r0 + 8][ks + t + 4];
            }
#pragma unroll
            for (int nf = 0; nf < 4; nf++) {
                int c0 = wn * 32 + nf * 8 + g;
                b[nf][0] = Ws[c0][ks + t];
                b[nf][1] = Ws[c0][ks + t + 4];
            }
#pragma unroll
            for (int mf = 0; mf < 2; mf++)
#pragma unroll
                for (int nf = 0; nf < 4; nf++)
                    mma_tf32(acc[mf][nf], a[mf][0], a[mf][1], a[mf][2], a[mf][3],
                             b[nf][0], b[nf][1]);
        }
        __syncthreads();
    }

#pragma unroll
    for (int mf = 0; mf < 2; mf++) {
        int row = m0 + wm * 32 + mf * 16 + g;
#pragma unroll
        for (int nf = 0; nf < 4; nf++) {
            int col = n0 + wn * 32 + nf * 8 + 2 * t;
            float b0 = bias[col], b1 = bias[col + 1];
            float v0 = acc[mf][nf][0] + b0;
            float v1 = acc[mf][nf][1] + b1;
            float v2 = acc[mf][nf][2] + b0;
            float v3 = acc[mf][nf][3] + b1;
            if (act) { v0 = lrelu(v0); v1 = lrelu(v1); v2 = lrelu(v2); v3 = lrelu(v3); }
            *reinterpret_cast<float2*>(&C[(size_t)row * NH + col])       = make_float2(v0, v1);
            *reinterpret_cast<float2*>(&C[(size_t)(row + 8) * NH + col]) = make_float2(v2, v3);
        }
    }
}

// ===========================================================================
extern "C" void kernel_launch(void* const* d_in, const int* in_sizes, int n_in,
                              void* d_out, int out_size)
{
    (void)in_sizes; (void)n_in; (void)out_size;
    const float* x    = (const float*)d_in[0];
    const float* y    = (const float*)d_in[1];
    const float* fc_w = (const float*)d_in[2];
    const float* fc_b = (const float*)d_in[3];
    const float* q_w  = (const float*)d_in[4];
    const float* q_b  = (const float*)d_in[5];
    const float* k_w  = (const float*)d_in[6];
    const float* k_b  = (const float*)d_in[7];
    const float* v_w  = (const float*)d_in[8];
    const float* v_b  = (const float*)d_in[9];
    float* out = (float*)d_out;

    float *p_xh, *p_q;
    cudaGetSymbolAddress((void**)&p_xh, g_xh);
    cudaGetSymbolAddress((void**)&p_q,  g_q);

    cudaFuncSetAttribute(fused, cudaFuncAttributeMaxDynamicSharedMemorySize, SMEM_FUSED);

    // 0) weights f32 -> fp16                        (~6 MB traffic)
    wcvt<<<256, 256>>>(fc_w, k_w, v_w);
    // 1) xh = lrelu(x @ fc_w^T + fc_b)              [2048, 512]  (tf32)
    gemm512_act<<<dim3(8, NB / 128), 256>>>(x, fc_w, fc_b, p_xh, 1);
    // 2) q = xh @ q_w^T + q_b                       [2048, 512]  (tf32)
    gemm512_act<<<dim3(8, NB / 128), 256>>>(p_xh, q_w, q_b, p_q, 0);
    // 3) fused per-batch: yh (SMEM-resident) + kv GEMM + register softmax -> out
    fused<<<NB, 256, SMEM_FUSED>>>(y, fc_b, k_b, v_b, out);
}

// round 15
// speedup vs baseline: 2.0119x; 1.0280x over previous
#include <cuda_runtime.h>
#include <cuda_fp16.h>
#include <cstdint>

#define ALPHA 0.2f

// Shapes (fixed by the problem)
#define NB   2048      // batch
#define NL   128       // neighbors
#define ND   512       // IN_DIM
#define NH   512       // HID

// Scratch (device globals: allocation-free by harness rules)
__device__ __align__(16) float  g_xh[NB * NH];        // 4 MB
__device__ __align__(16) float  g_q [NB * NH];        // 4 MB
__device__ __align__(16) __half g_fc16[ND * NH];      // 512 KB  fc_w fp16
__device__ __align__(16) __half g_kw16[NH * NH];      // 512 KB  k_w fp16
__device__ __align__(16) __half g_vw16[NH * NH];      // 512 KB  v_w fp16

// ===========================================================================
// Helpers
// ===========================================================================
__device__ __forceinline__ float lrelu(float v) { return v > 0.0f ? v : ALPHA * v; }

__device__ __forceinline__ unsigned f2tf32(float x) {
    unsigned r;
    asm("cvt.rna.tf32.f32 %0, %1;" : "=r"(r) : "f"(x));
    return r;
}
__device__ __forceinline__ unsigned pack2(float a, float b) {
    __half2 h = __floats2half2_rn(a, b);
    return reinterpret_cast<unsigned&>(h);
}
__device__ __forceinline__ uint32_t smem_u32(const void* p) {
    uint32_t a;
    asm("{ .reg .u64 t; cvta.to.shared.u64 t, %1; cvt.u32.u64 %0, t; }" : "=r"(a) : "l"(p));
    return a;
}
__device__ __forceinline__ void ldmx4(uint32_t r[4], uint32_t addr) {
    asm volatile("ldmatrix.sync.aligned.m8n8.x4.shared.b16 {%0,%1,%2,%3}, [%4];"
                 : "=r"(r[0]), "=r"(r[1]), "=r"(r[2]), "=r"(r[3]) : "r"(addr));
}
__device__ __forceinline__ void mma_f16(float c[4], const uint32_t a[4],
                                        uint32_t b0, uint32_t b1) {
    asm volatile("mma.sync.aligned.m16n8k16.row.col.f32.f16.f16.f32 "
                 "{%0,%1,%2,%3}, {%4,%5,%6,%7}, {%8,%9}, {%0,%1,%2,%3};"
                 : "+f"(c[0]), "+f"(c[1]), "+f"(c[2]), "+f"(c[3])
                 : "r"(a[0]), "r"(a[1]), "r"(a[2]), "r"(a[3]), "r"(b0), "r"(b1));
}
__device__ __forceinline__ void cpa16(uint32_t dst, const void* src) {
    asm volatile("cp.async.cg.shared.global [%0], [%1], 16;" :: "r"(dst), "l"(src));
}
#define CP_COMMIT asm volatile("cp.async.commit_group;" ::: "memory")
#define CP_WAIT1  asm volatile("cp.async.wait_group 1;" ::: "memory")
#define CP_WAIT0  asm volatile("cp.async.wait_group 0;" ::: "memory")

// 16B-segment swizzle (128B rows, 8 segments): seg' = seg ^ (row & 7)
// ldmatrix address for an 8x8 fp16 tile at (rowbase, colbyte)
__device__ __forceinline__ uint32_t ldm_addr(uint32_t base, int rowbase, int colbyte, int lane) {
    int mi = lane >> 3;
    int r  = rowbase + (mi & 1) * 8 + (lane & 7);
    unsigned off = (unsigned)(r * 128 + colbyte + (mi >> 1) * 16);
    return base + (off ^ ((off >> 3) & 0x70));
}

// SMEM layout (offsets from 128B-aligned base):
//   YH tiles: 8 x [128][64] fp16 swizzled, tile k at k*16384      [0, 131072)
//   Phase 1: B bufs (x3) at 131072+i*16384, A bufs (x3) at 180224+i*16384
//   Phase 2: kv pair bufs (x3, 32 KB each) at 131072+i*32768      [131072, 229376)
//   sred2 (softmax scratch, 2 KB) at 229376                       [229376, 231424)
#define YH_OFF(k)   ((k) * 16384)
#define B_OFF(i)    (131072 + (i) * 16384)
#define A_OFF(i)    (180224 + (i) * 16384)
#define PAIR_OFF(i) (131072 + (i) * 32768)
#define SRED_OFF    229376
#define SMEM_FUSED  (229376 + 2048 + 128)

// ===========================================================================
// Weight pre-convert: fc_w / k_w / v_w f32 -> fp16
// ===========================================================================
__global__ void wcvt(const float* __restrict__ fc, const float* __restrict__ kw,
                     const float* __restrict__ vw) {
    int i = blockIdx.x * blockDim.x + threadIdx.x;     // 0..65535, 4 floats each
    float4 a = *reinterpret_cast<const float4*>(fc + (size_t)i * 4);
    float4 b = *reinterpret_cast<const float4*>(kw + (size_t)i * 4);
    float4 c = *reinterpret_cast<const float4*>(vw + (size_t)i * 4);
    uint2 ua = make_uint2(pack2(a.x, a.y), pack2(a.z, a.w));
    uint2 ub = make_uint2(pack2(b.x, b.y), pack2(b.z, b.w));
    uint2 uc = make_uint2(pack2(c.x, c.y), pack2(c.z, c.w));
    *reinterpret_cast<uint2*>(&g_fc16[(size_t)i * 4]) = ua;
    *reinterpret_cast<uint2*>(&g_kw16[(size_t)i * 4]) = ub;
    *reinterpret_cast<uint2*>(&g_vw16[(size_t)i * 4]) = uc;
}

// ===========================================================================
// Fused per-batch kernel:
//   Phase 1: yh_b = lrelu(y_b @ fc_w^T + fc_b) -> SMEM fp16 (swizzled tiles)
//   Phase 2: 4x { paired kv chunk GEMM (2x64 features) + register softmax }
// ===========================================================================
__global__ __launch_bounds__(256, 1) void fused(
    const float* __restrict__ y, const float* __restrict__ fc_b,
    const float* __restrict__ kb, const float* __restrict__ vb,
    float* __restrict__ out)
{
    extern __shared__ char smem_raw[];
    char* sm = smem_raw + ((128 - ((uintptr_t)smem_raw & 127)) & 127);
    const uint32_t sb = smem_u32(sm);

    const int tid = threadIdx.x, warp = tid >> 5, lane = tid & 31;
    const int g = lane >> 2, t = lane & 3;
    const int wm = warp & 1, wn = warp >> 1;            // 2 x 4 warp grid
    const int bb = blockIdx.x;
    const float* yb = y + (size_t)bb * NL * ND;

    // acc2[u][mf][nf][i]; phase 1 uses acc2[0] only.
    float acc2[2][4][4][4];
    uint4 ra[4];

    // Phase-1 A: y f32 -> fp16 into registers
    auto ldgA = [&](int c) {
#pragma unroll
        for (int i = 0; i < 4; i++) {
            int idx = i * 256 + tid;
            int r = idx >> 3, s = idx & 7;
            const float* p = yb + (size_t)r * ND + c * 64 + s * 8;
            float4 a0 = *reinterpret_cast<const float4*>(p);
            float4 a1 = *reinterpret_cast<const float4*>(p + 4);
            ra[i] = make_uint4(pack2(a0.x, a0.y), pack2(a0.z, a0.w),
                               pack2(a1.x, a1.y), pack2(a1.z, a1.w));
        }
    };
    auto stsA = [&](int buf) {
#pragma unroll
        for (int i = 0; i < 4; i++) {
            int idx = i * 256 + tid;
            int r = idx >> 3, s = idx & 7;
            unsigned off = (unsigned)(r * 128 + ((s ^ (r & 7)) * 16));
            *reinterpret_cast<uint4*>(sm + A_OFF(buf) + off) = ra[i];
        }
    };
    // Phase-1 B: fc16 rows [nt*128, +128) via cp.async
    auto cpB1 = [&](int buf, int c, int nt) {
#pragma unroll
        for (int i = 0; i < 4; i++) {
            int idx = i * 256 + tid;
            int r = idx >> 3, s = idx & 7;
            const __half* src = g_fc16 + (size_t)(nt * 128 + r) * NH + c * 64 + s * 8;
            unsigned off = (unsigned)(r * 128 + ((s ^ (r & 7)) * 16));
            cpa16(sb + B_OFF(buf) + off, src);
        }
    };
    // Phase-2 paired B (kv-interleaved, 2 ht groups of 64 features = 32 KB):
    // sub-tile u in {0,1}: row 2j = k_w[hp*128+u*64+j], row 2j+1 = v_w[...]
    auto cpB2 = [&](int buf, int c, int hp) {
#pragma unroll
        for (int i = 0; i < 8; i++) {
            int idx = i * 256 + tid;
            int r = idx >> 3, s = idx & 7;       // r in 0..255
            int u = r >> 7, rr = r & 127;
            int f = hp * 128 + u * 64 + (rr >> 1);
            const __half* base = (rr & 1) ? g_vw16 : g_kw16;
            const __half* src = base + (size_t)f * NH + c * 64 + s * 8;
            unsigned off = (unsigned)(rr * 128 + ((s ^ (rr & 7)) * 16));
            cpa16(sb + PAIR_OFF(buf) + u * 16384 + off, src);
        }
    };
    // Phase-1 mmac (single B tile into acc2[0])
    auto mmac1 = [&](uint32_t Abase, uint32_t Bbase) {
#pragma unroll
        for (int ks = 0; ks < 4; ks++) {
            uint32_t a[4][4], b[2][4];
#pragma unroll
            for (int mf = 0; mf < 4; mf++)
                ldmx4(a[mf], ldm_addr(Abase, wm * 64 + mf * 16, ks * 32, lane));
#pragma unroll
            for (int np = 0; np < 2; np++)
                ldmx4(b[np], ldm_addr(Bbase, wn * 32 + np * 16, ks * 32, lane));
#pragma unroll
            for (int mf = 0; mf < 4; mf++)
#pragma unroll
                for (int nf = 0; nf < 4; nf++)
                    mma_f16(acc2[0][mf][nf], a[mf],
                            b[nf >> 1][nf & 1], b[nf >> 1][(nf & 1) + 2]);
        }
    };
    // Phase-2 paired mmac: A fragments loaded once, used for both sub-tiles
    auto mmac2 = [&](uint32_t Abase, uint32_t Bbase) {
#pragma unroll
        for (int ks = 0; ks < 4; ks++) {
            uint32_t a[4][4];
#pragma unroll
            for (int mf = 0; mf < 4; mf++)
                ldmx4(a[mf], ldm_addr(Abase, wm * 64 + mf * 16, ks * 32, lane));
#pragma unroll
            for (int u = 0; u < 2; u++) {
                uint32_t b[2][4];
#pragma unroll
                for (int np = 0; np < 2; np++)
                    ldmx4(b[np], ldm_addr(Bbase + u * 16384, wn * 32 + np * 16,
                                          ks * 32, lane));
#pragma unroll
                for (int mf = 0; mf < 4; mf++)
#pragma unroll
                    for (int nf = 0; nf < 4; nf++)
                        mma_f16(acc2[u][mf][nf], a[mf],
                                b[nf >> 1][nf & 1], b[nf >> 1][(nf & 1) + 2]);
            }
        }
    };

    // ---------------- Phase 1: yh_b -> SMEM ----------------
    for (int nt = 0; nt < 4; nt++) {
#pragma unroll
        for (int mf = 0; mf < 4; mf++)
#pragma unroll
            for (int nf = 0; nf < 4; nf++)
#pragma unroll
                for (int i = 0; i < 4; i++) acc2[0][mf][nf][i] = 0.0f;

        ldgA(0); stsA(0); cpB1(0, 0, nt); CP_COMMIT;
        ldgA(1); stsA(1); cpB1(1, 1, nt); CP_COMMIT;
        ldgA(2);
        for (int c = 0; c < 8; c++) {
            if (c < 7) { CP_WAIT1; } else { CP_WAIT0; }
            __syncthreads();
            if (c + 2 < 8) { stsA((c + 2) % 3); cpB1((c + 2) % 3, c + 2, nt); CP_COMMIT; }
            if (c + 3 < 8) ldgA(c + 3);
            mmac1(sb + A_OFF(c % 3), sb + B_OFF(c % 3));
        }
        // epilogue: bias + lrelu -> fp16 into YH tiles (swizzled)
#pragma unroll
        for (int mf = 0; mf < 4; mf++) {
            int row = wm * 64 + mf * 16 + g;
#pragma unroll
            for (int nf = 0; nf < 4; nf++) {
                int colg = nt * 128 + wn * 32 + nf * 8 + 2 * t;
                int tile = colg >> 6, cc = colg & 63;
                float b0 = fc_b[colg], b1 = fc_b[colg + 1];
                __half2 h0 = __floats2half2_rn(lrelu(acc2[0][mf][nf][0] + b0),
                                               lrelu(acc2[0][mf][nf][1] + b1));
                __half2 h1 = __floats2half2_rn(lrelu(acc2[0][mf][nf][2] + b0),
                                               lrelu(acc2[0][mf][nf][3] + b1));
                unsigned o0 = (unsigned)(row * 128 + cc * 2);
                o0 ^= (o0 >> 3) & 0x70;
                *reinterpret_cast<__half2*>(sm + YH_OFF(tile) + o0) = h0;
                unsigned o1 = (unsigned)((row + 8) * 128 + cc * 2);
                o1 ^= (o1 >> 3) & 0x70;
                *reinterpret_cast<__half2*>(sm + YH_OFF(tile) + o1) = h1;
            }
        }
        __syncthreads();
    }

    // ---------------- Phase 2: paired kv chunks + register softmax ----------
    // sred2 layout: [(wm*2+u)*64 + f] * 2 + {z, h}  (2 KB)
    float* sred2 = reinterpret_cast<float*>(sm + SRED_OFF);

    for (int hp = 0; hp < 4; hp++) {
#pragma unroll
        for (int u = 0; u < 2; u++)
#pragma unroll
            for (int mf = 0; mf < 4; mf++)
#pragma unroll
                for (int nf = 0; nf < 4; nf++)
#pragma unroll
                    for (int i = 0; i < 4; i++) acc2[u][mf][nf][i] = 0.0f;

        cpB2(0, 0, hp); CP_COMMIT;
        cpB2(1, 1, hp); CP_COMMIT;
        for (int c = 0; c < 8; c++) {
            if (c < 7) { CP_WAIT1; } else { CP_WAIT0; }
            __syncthreads();
            if (c + 2 < 8) { cpB2((c + 2) % 3, c + 2, hp); CP_COMMIT; }
            mmac2(sb + YH_OFF(c), sb + PAIR_OFF(c % 3));
        }

        // Register epilogue (max-free softmax: |att| << 1 so exp is safe;
        // z and h both scale by the same factor, result identical).
        // Fragment: c[0]=key(row), c[1]=vec(row), c[2]=key(row+8), c[3]=vec(row+8)
        // feature f = wn*16 + nf*4 + t within sub-tile u.
#pragma unroll
        for (int u = 0; u < 2; u++) {
#pragma unroll
            for (int nf = 0; nf < 4; nf++) {
                int h = hp * 128 + u * 64 + wn * 16 + nf * 4 + t;
                float qv  = g_q[(size_t)bb * NH + h];
                float kbv = kb[h];
                float vbv = vb[h];
                float z = 0.0f, hs = 0.0f;
#pragma unroll
                for (int mf = 0; mf < 4; mf++) {
                    float e0 = __expf((acc2[u][mf][nf][0] + kbv) * qv);
                    z += e0;
                    hs += lrelu((acc2[u][mf][nf][1] + vbv) * e0);
                    float e1 = __expf((acc2[u][mf][nf][2] + kbv) * qv);
                    z += e1;
                    hs += lrelu((acc2[u][mf][nf][3] + vbv) * e1);
                }
                z  += __shfl_xor_sync(0xffffffffu, z, 4);
                z  += __shfl_xor_sync(0xffffffffu, z, 8);
                z  += __shfl_xor_sync(0xffffffffu, z, 16);
                hs += __shfl_xor_sync(0xffffffffu, hs, 4);
                hs += __shfl_xor_sync(0xffffffffu, hs, 8);
                hs += __shfl_xor_sync(0xffffffffu, hs, 16);
                if (g == 0) {
                    int f = wn * 16 + nf * 4 + t;
                    sred2[((wm * 2 + u) * 64 + f) * 2]     = z;
                    sred2[((wm * 2 + u) * 64 + f) * 2 + 1] = hs;
                }
            }
        }
        __syncthreads();

        if (wm == 0 && g == 0) {
#pragma unroll
            for (int u = 0; u < 2; u++)
#pragma unroll
                for (int nf = 0; nf < 4; nf++) {
                    int f = wn * 16 + nf * 4 + t;
                    float z  = sred2[(u * 64 + f) * 2]     + sred2[((2 + u) * 64 + f) * 2];
                    float hs = sred2[(u * 64 + f) * 2 + 1] + sred2[((2 + u) * 64 + f) * 2 + 1];
                    int h = hp * 128 + u * 64 + f;
                    out[(size_t)bb * NH + h] =
                        (g_xh[(size_t)bb * NH + h] + hs / z) * 0.5f;
                }
        }
        // Next hp's first chunk barrier orders sred2 reuse and pair-buf refill.
    }
}

// ===========================================================================
// Small GEMMs (xh, q): legacy tf32 mma.sync kernel (known-good).
// ===========================================================================
__device__ __forceinline__ void mma_tf32(float c[4],
                                         unsigned a0, unsigned a1, unsigned a2, unsigned a3,
                                         unsigned b0, unsigned b1) {
    asm volatile(
        "mma.sync.aligned.m16n8k8.row.col.f32.tf32.tf32.f32 "
        "{%0,%1,%2,%3}, {%4,%5,%6,%7}, {%8,%9}, {%0,%1,%2,%3};\n"
        : "+f"(c[0]), "+f"(c[1]), "+f"(c[2]), "+f"(c[3])
        : "r"(a0), "r"(a1), "r"(a2), "r"(a3), "r"(b0), "r"(b1));
}

__global__ __launch_bounds__(256) void gemm512_act(
    const float* __restrict__ A, const float* __restrict__ W,
    const float* __restrict__ bias, float* __restrict__ C, int act)
{
    __shared__ unsigned As[128][36];
    __shared__ unsigned Ws[64][36];

    const int tid  = threadIdx.x;
    const int warp = tid >> 5, lane = tid & 31;
    const int g = lane >> 2, t = lane & 3;
    const int wm = warp & 3, wn = warp >> 2;
    const int m0 = blockIdx.y * 128;
    const int n0 = blockIdx.x * 64;

    float acc[2][4][4];
#pragma unroll
    for (int mf = 0; mf < 2; mf++)
#pragma unroll
        for (int nf = 0; nf < 4; nf++)
#pragma unroll
            for (int i = 0; i < 4; i++) acc[mf][nf][i] = 0.0f;

    for (int k0 = 0; k0 < ND; k0 += 32) {
#pragma unroll
        for (int i = 0; i < 4; i++) {
            int idx = i * 256 + tid;
            int r = idx >> 3, c4 = (idx & 7) * 4;
            float4 v = *reinterpret_cast<const float4*>(&A[(size_t)(m0 + r) * ND + k0 + c4]);
            uint4 u = make_uint4(f2tf32(v.x), f2tf32(v.y), f2tf32(v.z), f2tf32(v.w));
            *reinterpret_cast<uint4*>(&As[r][c4]) = u;
        }
#pragma unroll
        for (int i = 0; i < 2; i++) {
            int idx = i * 256 + tid;
            int r = idx >> 3, c4 = (idx & 7) * 4;
            float4 v = *reinterpret_cast<const float4*>(&W[(size_t)(n0 + r) * ND + k0 + c4]);
            uint4 u = make_uint4(f2tf32(v.x), f2tf32(v.y), f2tf32(v.z), f2tf32(v.w));
            *reinterpret_cast<uint4*>(&Ws[r][c4]) = u;
        }
        __syncthreads();

#pragma unroll
        for (int ks = 0; ks < 32; ks += 8) {
            unsigned a[2][4], b[4][2];
#pragma unroll
            for (int mf = 0; mf < 2; mf++) {
                int r0 = wm * 32 + mf * 16 + g;
                a[mf][0] = As[r0    ][ks + t];
                a[mf][1] = As[r0 + 8][ks + t];
                a[mf][2] = As[r0    ][ks + t + 4];
                a[mf][3] = As[r0 + 8][ks + t + 4];
            }
#pragma unroll
            for (int nf = 0; nf < 4; nf++) {
                int c0 = wn * 32 + nf * 8 + g;
                b[nf][0] = Ws[c0][ks + t];
                b[nf][1] = Ws[c0][ks + t + 4];
            }
#pragma unroll
            for (int mf = 0; mf < 2; mf++)
#pragma unroll
                for (int nf = 0; nf < 4; nf++)
                    mma_tf32(acc[mf][nf], a[mf][0], a[mf][1], a[mf][2], a[mf][3],
                             b[nf][0], b[nf][1]);
        }
        __syncthreads();
    }

#pragma unroll
    for (int mf = 0; mf < 2; mf++) {
        int row = m0 + wm * 32 + mf * 16 + g;
#pragma unroll
        for (int nf = 0; nf < 4; nf++) {
            int col = n0 + wn * 32 + nf * 8 + 2 * t;
            float b0 = bias[col], b1 = bias[col + 1];
            float v0 = acc[mf][nf][0] + b0;
            float v1 = acc[mf][nf][1] + b1;
            float v2 = acc[mf][nf][2] + b0;
            float v3 = acc[mf][nf][3] + b1;
            if (act) { v0 = lrelu(v0); v1 = lrelu(v1); v2 = lrelu(v2); v3 = lrelu(v3); }
            *reinterpret_cast<float2*>(&C[(size_t)row * NH + col])       = make_float2(v0, v1);
            *reinterpret_cast<float2*>(&C[(size_t)(row + 8) * NH + col]) = make_float2(v2, v3);
        }
    }
}

// ===========================================================================
extern "C" void kernel_launch(void* const* d_in, const int* in_sizes, int n_in,
                              void* d_out, int out_size)
{
    (void)in_sizes; (void)n_in; (void)out_size;
    const float* x    = (const float*)d_in[0];
    const float* y    = (const float*)d_in[1];
    const float* fc_w = (const float*)d_in[2];
    const float* fc_b = (const float*)d_in[3];
    const float* q_w  = (const float*)d_in[4];
    const float* q_b  = (const float*)d_in[5];
    const float* k_w  = (const float*)d_in[6];
    const float* k_b  = (const float*)d_in[7];
    const float* v_w  = (const float*)d_in[8];
    const float* v_b  = (const float*)d_in[9];
    float* out = (float*)d_out;

    float *p_xh, *p_q;
    cudaGetSymbolAddress((void**)&p_xh, g_xh);
    cudaGetSymbolAddress((void**)&p_q,  g_q);

    cudaFuncSetAttribute(fused, cudaFuncAttributeMaxDynamicSharedMemorySize, SMEM_FUSED);

    // 0) weights f32 -> fp16                        (~6 MB traffic)
    wcvt<<<256, 256>>>(fc_w, k_w, v_w);
    // 1) xh = lrelu(x @ fc_w^T + fc_b)              [2048, 512]  (tf32)
    gemm512_act<<<dim3(8, NB / 128), 256>>>(x, fc_w, fc_b, p_xh, 1);
    // 2) q = xh @ q_w^T + q_b                       [2048, 512]  (tf32)
    gemm512_act<<<dim3(8, NB / 128), 256>>>(p_xh, q_w, q_b, p_q, 0);
    // 3) fused per-batch: yh (SMEM-resident) + paired kv GEMM + softmax -> out
    fused<<<NB, 256, SMEM_FUSED>>>(y, fc_b, k_b, v_b, out);
}

// round 16
// speedup vs baseline: 2.1764x; 1.0818x over previous
#include <cuda_runtime.h>
#include <cuda_fp16.h>
#include <cstdint>

#define ALPHA 0.2f

// Shapes (fixed by the problem)
#define NB   2048      // batch
#define NL   128       // neighbors
#define ND   512       // IN_DIM
#define NH   512       // HID

// Scratch (device globals: allocation-free by harness rules)
__device__ __align__(16) float  g_xh[NB * NH];        // 4 MB
__device__ __align__(16) float  g_q [NB * NH];        // 4 MB
__device__ __align__(16) __half g_fc16[ND * NH];      // 512 KB  fc_w fp16
__device__ __align__(16) __half g_kw16[NH * NH];      // 512 KB  k_w fp16
__device__ __align__(16) __half g_vw16[NH * NH];      // 512 KB  v_w fp16

// ===========================================================================
// Helpers
// ===========================================================================
__device__ __forceinline__ float lrelu(float v) { return v > 0.0f ? v : ALPHA * v; }

__device__ __forceinline__ unsigned f2tf32(float x) {
    unsigned r;
    asm("cvt.rna.tf32.f32 %0, %1;" : "=r"(r) : "f"(x));
    return r;
}
__device__ __forceinline__ unsigned pack2(float a, float b) {
    __half2 h = __floats2half2_rn(a, b);
    return reinterpret_cast<unsigned&>(h);
}
__device__ __forceinline__ uint32_t smem_u32(const void* p) {
    uint32_t a;
    asm("{ .reg .u64 t; cvta.to.shared.u64 t, %1; cvt.u32.u64 %0, t; }" : "=r"(a) : "l"(p));
    return a;
}
__device__ __forceinline__ void ldmx4(uint32_t r[4], uint32_t addr) {
    asm volatile("ldmatrix.sync.aligned.m8n8.x4.shared.b16 {%0,%1,%2,%3}, [%4];"
                 : "=r"(r[0]), "=r"(r[1]), "=r"(r[2]), "=r"(r[3]) : "r"(addr));
}
__device__ __forceinline__ void mma_f16(float c[4], const uint32_t a[4],
                                        uint32_t b0, uint32_t b1) {
    asm volatile("mma.sync.aligned.m16n8k16.row.col.f32.f16.f16.f32 "
                 "{%0,%1,%2,%3}, {%4,%5,%6,%7}, {%8,%9}, {%0,%1,%2,%3};"
                 : "+f"(c[0]), "+f"(c[1]), "+f"(c[2]), "+f"(c[3])
                 : "r"(a[0]), "r"(a[1]), "r"(a[2]), "r"(a[3]), "r"(b0), "r"(b1));
}
__device__ __forceinline__ void cpa16(uint32_t dst, const void* src) {
    asm volatile("cp.async.cg.shared.global [%0], [%1], 16;" :: "r"(dst), "l"(src));
}
#define CP_COMMIT asm volatile("cp.async.commit_group;" ::: "memory")
#define CP_WAIT1  asm volatile("cp.async.wait_group 1;" ::: "memory")
#define CP_WAIT0  asm volatile("cp.async.wait_group 0;" ::: "memory")

// 16B-segment swizzle (128B rows, 8 segments): seg' = seg ^ (row & 7)
// ldmatrix address for an 8x8 fp16 tile at (rowbase, colbyte)
__device__ __forceinline__ uint32_t ldm_addr(uint32_t base, int rowbase, int colbyte, int lane) {
    int mi = lane >> 3;
    int r  = rowbase + (mi & 1) * 8 + (lane & 7);
    unsigned off = (unsigned)(r * 128 + colbyte + (mi >> 1) * 16);
    return base + (off ^ ((off >> 3) & 0x70));
}

// SMEM layout (offsets from 128B-aligned base):
//   YH tiles: 8 x [128][64] fp16 swizzled, tile k at k*16384      [0, 131072)
//   Phase 1: B bufs (x3) at 131072+i*16384, A bufs (x3) at 180224+i*16384
//   Phase 2: kv pair bufs (x3, 32 KB each) at 131072+i*32768      [131072, 229376)
//   sred2 (4 KB softmax scratch) ALIASES pair buf 2 (dead during epilogue).
#define YH_OFF(k)   ((k) * 16384)
#define B_OFF(i)    (131072 + (i) * 16384)
#define A_OFF(i)    (180224 + (i) * 16384)
#define PAIR_OFF(i) (131072 + (i) * 32768)
#define SRED_OFF    PAIR_OFF(2)
#define SMEM_FUSED  (229376 + 128)

#define NT_FUSED 512   // 16 warps

// ===========================================================================
// Weight pre-convert: fc_w / k_w / v_w f32 -> fp16
// ===========================================================================
__global__ void wcvt(const float* __restrict__ fc, const float* __restrict__ kw,
                     const float* __restrict__ vw) {
    int i = blockIdx.x * blockDim.x + threadIdx.x;     // 0..65535, 4 floats each
    float4 a = *reinterpret_cast<const float4*>(fc + (size_t)i * 4);
    float4 b = *reinterpret_cast<const float4*>(kw + (size_t)i * 4);
    float4 c = *reinterpret_cast<const float4*>(vw + (size_t)i * 4);
    uint2 ua = make_uint2(pack2(a.x, a.y), pack2(a.z, a.w));
    uint2 ub = make_uint2(pack2(b.x, b.y), pack2(b.z, b.w));
    uint2 uc = make_uint2(pack2(c.x, c.y), pack2(c.z, c.w));
    *reinterpret_cast<uint2*>(&g_fc16[(size_t)i * 4]) = ua;
    *reinterpret_cast<uint2*>(&g_kw16[(size_t)i * 4]) = ub;
    *reinterpret_cast<uint2*>(&g_vw16[(size_t)i * 4]) = uc;
}

// ===========================================================================
// Fused per-batch kernel (512 threads, 16 warps as 4x4):
//   Phase 1: yh_b = lrelu(y_b @ fc_w^T + fc_b) -> SMEM fp16 (swizzled tiles)
//   Phase 2: 4x { paired kv chunk GEMM (2x64 features) + register softmax }
// ===========================================================================
__global__ __launch_bounds__(NT_FUSED, 1) void fused(
    const float* __restrict__ y, const float* __restrict__ fc_b,
    const float* __restrict__ kb, const float* __restrict__ vb,
    float* __restrict__ out)
{
    extern __shared__ char smem_raw[];
    char* sm = smem_raw + ((128 - ((uintptr_t)smem_raw & 127)) & 127);
    const uint32_t sb = smem_u32(sm);

    const int tid = threadIdx.x, warp = tid >> 5, lane = tid & 31;
    const int g = lane >> 2, t = lane & 3;
    const int wm = warp & 3, wn = warp >> 2;            // 4 x 4 warp grid
    const int bb = blockIdx.x;
    const float* yb = y + (size_t)bb * NL * ND;

    // Phase 1: acc1[mf][nf][i], warp tile 32(m) x 32(n)
    // Phase 2: acc2[u][mf][nf][i], per sub-tile 32(L) x 32(kv-cols)
    float acc2[2][2][4][4];
    uint4 ra[2];

    // Phase-1 A: y f32 -> fp16 into registers (128x64 halves, 512 thr -> 2 iters)
    auto ldgA = [&](int c) {
#pragma unroll
        for (int i = 0; i < 2; i++) {
            int idx = i * NT_FUSED + tid;
            int r = idx >> 3, s = idx & 7;
            const float* p = yb + (size_t)r * ND + c * 64 + s * 8;
            float4 a0 = *reinterpret_cast<const float4*>(p);
            float4 a1 = *reinterpret_cast<const float4*>(p + 4);
            ra[i] = make_uint4(pack2(a0.x, a0.y), pack2(a0.z, a0.w),
                               pack2(a1.x, a1.y), pack2(a1.z, a1.w));
        }
    };
    auto stsA = [&](int buf) {
#pragma unroll
        for (int i = 0; i < 2; i++) {
            int idx = i * NT_FUSED + tid;
            int r = idx >> 3, s = idx & 7;
            unsigned off = (unsigned)(r * 128 + ((s ^ (r & 7)) * 16));
            *reinterpret_cast<uint4*>(sm + A_OFF(buf) + off) = ra[i];
        }
    };
    // Phase-1 B: fc16 rows [nt*128, +128) via cp.async
    auto cpB1 = [&](int buf, int c, int nt) {
#pragma unroll
        for (int i = 0; i < 2; i++) {
            int idx = i * NT_FUSED + tid;
            int r = idx >> 3, s = idx & 7;
            const __half* src = g_fc16 + (size_t)(nt * 128 + r) * NH + c * 64 + s * 8;
            unsigned off = (unsigned)(r * 128 + ((s ^ (r & 7)) * 16));
            cpa16(sb + B_OFF(buf) + off, src);
        }
    };
    // Phase-2 paired B (kv-interleaved, 2 groups of 64 features = 32 KB)
    auto cpB2 = [&](int buf, int c, int hp) {
#pragma unroll
        for (int i = 0; i < 4; i++) {
            int idx = i * NT_FUSED + tid;
            int r = idx >> 3, s = idx & 7;       // r in 0..255
            int u = r >> 7, rr = r & 127;
            int f = hp * 128 + u * 64 + (rr >> 1);
            const __half* base = (rr & 1) ? g_vw16 : g_kw16;
            const __half* src = base + (size_t)f * NH + c * 64 + s * 8;
            unsigned off = (unsigned)(rr * 128 + ((s ^ (rr & 7)) * 16));
            cpa16(sb + PAIR_OFF(buf) + u * 16384 + off, src);
        }
    };
    // Phase-1 mmac: warp tile 32x32 into acc2[0]
    auto mmac1 = [&](uint32_t Abase, uint32_t Bbase) {
#pragma unroll
        for (int ks = 0; ks < 4; ks++) {
            uint32_t a[2][4], b[2][4];
#pragma unroll
            for (int mf = 0; mf < 2; mf++)
                ldmx4(a[mf], ldm_addr(Abase, wm * 32 + mf * 16, ks * 32, lane));
#pragma unroll
            for (int np = 0; np < 2; np++)
                ldmx4(b[np], ldm_addr(Bbase, wn * 32 + np * 16, ks * 32, lane));
#pragma unroll
            for (int mf = 0; mf < 2; mf++)
#pragma unroll
                for (int nf = 0; nf < 4; nf++)
                    mma_f16(acc2[0][mf][nf], a[mf],
                            b[nf >> 1][nf & 1], b[nf >> 1][(nf & 1) + 2]);
        }
    };
    // Phase-2 paired mmac: A fragments loaded once, used for both sub-tiles
    auto mmac2 = [&](uint32_t Abase, uint32_t Bbase) {
#pragma unroll
        for (int ks = 0; ks < 4; ks++) {
            uint32_t a[2][4];
#pragma unroll
            for (int mf = 0; mf < 2; mf++)
                ldmx4(a[mf], ldm_addr(Abase, wm * 32 + mf * 16, ks * 32, lane));
#pragma unroll
            for (int u = 0; u < 2; u++) {
                uint32_t b[2][4];
#pragma unroll
                for (int np = 0; np < 2; np++)
                    ldmx4(b[np], ldm_addr(Bbase + u * 16384, wn * 32 + np * 16,
                                          ks * 32, lane));
#pragma unroll
                for (int mf = 0; mf < 2; mf++)
#pragma unroll
                    for (int nf = 0; nf < 4; nf++)
                        mma_f16(acc2[u][mf][nf], a[mf],
                                b[nf >> 1][nf & 1], b[nf >> 1][(nf & 1) + 2]);
            }
        }
    };

    // ---------------- Phase 1: yh_b -> SMEM ----------------
    for (int nt = 0; nt < 4; nt++) {
#pragma unroll
        for (int mf = 0; mf < 2; mf++)
#pragma unroll
            for (int nf = 0; nf < 4; nf++)
#pragma unroll
                for (int i = 0; i < 4; i++) acc2[0][mf][nf][i] = 0.0f;

        ldgA(0); stsA(0); cpB1(0, 0, nt); CP_COMMIT;
        ldgA(1); stsA(1); cpB1(1, 1, nt); CP_COMMIT;
        ldgA(2);
        for (int c = 0; c < 8; c++) {
            if (c < 7) { CP_WAIT1; } else { CP_WAIT0; }
            __syncthreads();
            if (c + 2 < 8) { stsA((c + 2) % 3); cpB1((c + 2) % 3, c + 2, nt); CP_COMMIT; }
            if (c + 3 < 8) ldgA(c + 3);
            mmac1(sb + A_OFF(c % 3), sb + B_OFF(c % 3));
        }
        // epilogue: bias + lrelu -> fp16 into YH tiles (swizzled)
#pragma unroll
        for (int mf = 0; mf < 2; mf++) {
            int row = wm * 32 + mf * 16 + g;
#pragma unroll
            for (int nf = 0; nf < 4; nf++) {
                int colg = nt * 128 + wn * 32 + nf * 8 + 2 * t;
                int tile = colg >> 6, cc = colg & 63;
                float b0 = fc_b[colg], b1 = fc_b[colg + 1];
                __half2 h0 = __floats2half2_rn(lrelu(acc2[0][mf][nf][0] + b0),
                                               lrelu(acc2[0][mf][nf][1] + b1));
                __half2 h1 = __floats2half2_rn(lrelu(acc2[0][mf][nf][2] + b0),
                                               lrelu(acc2[0][mf][nf][3] + b1));
                unsigned o0 = (unsigned)(row * 128 + cc * 2);
                o0 ^= (o0 >> 3) & 0x70;
                *reinterpret_cast<__half2*>(sm + YH_OFF(tile) + o0) = h0;
                unsigned o1 = (unsigned)((row + 8) * 128 + cc * 2);
                o1 ^= (o1 >> 3) & 0x70;
                *reinterpret_cast<__half2*>(sm + YH_OFF(tile) + o1) = h1;
            }
        }
        __syncthreads();
    }

    // ---------------- Phase 2: paired kv chunks + register softmax ----------
    // sred2 aliases pair buf 2 (all its mainloop reads finish >= 2 barriers
    // before the epilogue; next hp's refill is ordered by the first mainloop
    // barrier). Layout: [((wm*2 + u)*64 + f)*2 + {z,h}]  -> 4 KB.
    float* sred2 = reinterpret_cast<float*>(sm + SRED_OFF);

    for (int hp = 0; hp < 4; hp++) {
#pragma unroll
        for (int u = 0; u < 2; u++)
#pragma unroll
            for (int mf = 0; mf < 2; mf++)
#pragma unroll
                for (int nf = 0; nf < 4; nf++)
#pragma unroll
                    for (int i = 0; i < 4; i++) acc2[u][mf][nf][i] = 0.0f;

        cpB2(0, 0, hp); CP_COMMIT;
        cpB2(1, 1, hp); CP_COMMIT;
        for (int c = 0; c < 8; c++) {
            if (c < 7) { CP_WAIT1; } else { CP_WAIT0; }
            __syncthreads();
            if (c + 2 < 8) { cpB2((c + 2) % 3, c + 2, hp); CP_COMMIT; }
            mmac2(sb + YH_OFF(c), sb + PAIR_OFF(c % 3));
        }

        // Register epilogue (max-free softmax: |att| << 1, exp safe in fp32;
        // z and h scale identically so the quotient is exact).
        // Fragment: c[0]=key(row), c[1]=vec(row), c[2]=key(row+8), c[3]=vec(row+8)
        // feature f = wn*16 + nf*4 + t within sub-tile u; rows = wm*32+mf*16+{g,g+8}.
#pragma unroll
        for (int u = 0; u < 2; u++) {
#pragma unroll
            for (int nf = 0; nf < 4; nf++) {
                int h = hp * 128 + u * 64 + wn * 16 + nf * 4 + t;
                float qv  = g_q[(size_t)bb * NH + h];
                float kbv = kb[h];
                float vbv = vb[h];
                float z = 0.0f, hs = 0.0f;
#pragma unroll
                for (int mf = 0; mf < 2; mf++) {
                    float e0 = __expf((acc2[u][mf][nf][0] + kbv) * qv);
                    z += e0;
                    hs += lrelu((acc2[u][mf][nf][1] + vbv) * e0);
                    float e1 = __expf((acc2[u][mf][nf][2] + kbv) * qv);
                    z += e1;
                    hs += lrelu((acc2[u][mf][nf][3] + vbv) * e1);
                }
                z  += __shfl_xor_sync(0xffffffffu, z, 4);
                z  += __shfl_xor_sync(0xffffffffu, z, 8);
                z  += __shfl_xor_sync(0xffffffffu, z, 16);
                hs += __shfl_xor_sync(0xffffffffu, hs, 4);
                hs += __shfl_xor_sync(0xffffffffu, hs, 8);
                hs += __shfl_xor_sync(0xffffffffu, hs, 16);
                if (g == 0) {
                    int f = wn * 16 + nf * 4 + t;
                    sred2[((wm * 2 + u) * 64 + f) * 2]     = z;
                    sred2[((wm * 2 + u) * 64 + f) * 2 + 1] = hs;
                }
            }
        }
        __syncthreads();

        if (wm == 0 && g == 0) {
#pragma unroll
            for (int u = 0; u < 2; u++)
#pragma unroll
                for (int nf = 0; nf < 4; nf++) {
                    int f = wn * 16 + nf * 4 + t;
                    float z = 0.0f, hs = 0.0f;
#pragma unroll
                    for (int w = 0; w < 4; w++) {
                        z  += sred2[((w * 2 + u) * 64 + f) * 2];
                        hs += sred2[((w * 2 + u) * 64 + f) * 2 + 1];
                    }
                    int h = hp * 128 + u * 64 + f;
                    out[(size_t)bb * NH + h] =
                        (g_xh[(size_t)bb * NH + h] + hs / z) * 0.5f;
                }
        }
        // Next hp's first chunk barrier orders sred2 reuse and pair-buf refill.
    }
}

// ===========================================================================
// Small GEMMs (xh, q): legacy tf32 mma.sync kernel (known-good).
// ===========================================================================
__device__ __forceinline__ void mma_tf32(float c[4],
                                         unsigned a0, unsigned a1, unsigned a2, unsigned a3,
                                         unsigned b0, unsigned b1) {
    asm volatile(
        "mma.sync.aligned.m16n8k8.row.col.f32.tf32.tf32.f32 "
        "{%0,%1,%2,%3}, {%4,%5,%6,%7}, {%8,%9}, {%0,%1,%2,%3};\n"
        : "+f"(c[0]), "+f"(c[1]), "+f"(c[2]), "+f"(c[3])
        : "r"(a0), "r"(a1), "r"(a2), "r"(a3), "r"(b0), "r"(b1));
}

__global__ __launch_bounds__(256) void gemm512_act(
    const float* __restrict__ A, const float* __restrict__ W,
    const float* __restrict__ bias, float* __restrict__ C, int act)
{
    __shared__ unsigned As[128][36];
    __shared__ unsigned Ws[64][36];

    const int tid  = threadIdx.x;
    const int warp = tid >> 5, lane = tid & 31;
    const int g = lane >> 2, t = lane & 3;
    const int wm = warp & 3, wn = warp >> 2;
    const int m0 = blockIdx.y * 128;
    const int n0 = blockIdx.x * 64;

    float acc[2][4][4];
#pragma unroll
    for (int mf = 0; mf < 2; mf++)
#pragma unroll
        for (int nf = 0; nf < 4; nf++)
#pragma unroll
            for (int i = 0; i < 4; i++) acc[mf][nf][i] = 0.0f;

    for (int k0 = 0; k0 < ND; k0 += 32) {
#pragma unroll
        for (int i = 0; i < 4; i++) {
            int idx = i * 256 + tid;
            int r = idx >> 3, c4 = (idx & 7) * 4;
            float4 v = *reinterpret_cast<const float4*>(&A[(size_t)(m0 + r) * ND + k0 + c4]);
            uint4 u = make_uint4(f2tf32(v.x), f2tf32(v.y), f2tf32(v.z), f2tf32(v.w));
            *reinterpret_cast<uint4*>(&As[r][c4]) = u;
        }
#pragma unroll
        for (int i = 0; i < 2; i++) {
            int idx = i * 256 + tid;
            int r = idx >> 3, c4 = (idx & 7) * 4;
            float4 v = *reinterpret_cast<const float4*>(&W[(size_t)(n0 + r) * ND + k0 + c4]);
            uint4 u = make_uint4(f2tf32(v.x), f2tf32(v.y), f2tf32(v.z), f2tf32(v.w));
            *reinterpret_cast<uint4*>(&Ws[r][c4]) = u;
        }
        __syncthreads();

#pragma unroll
        for (int ks = 0; ks < 32; ks += 8) {
            unsigned a[2][4], b[4][2];
#pragma unroll
            for (int mf = 0; mf < 2; mf++) {
                int r0 = wm * 32 + mf * 16 + g;
                a[mf][0] = As[r0    ][ks + t];
                a[mf][1] = As[r0 + 8][ks + t];
                a[mf][2] = As[r0    ][ks + t + 4];
                a[mf][3] = As[r0 + 8][ks + t + 4];
            }
#pragma unroll
            for (int nf = 0; nf < 4; nf++) {
                int c0 = wn * 32 + nf * 8 + g;
                b[nf][0] = Ws[c0][ks + t];
                b[nf][1] = Ws[c0][ks + t + 4];
            }
#pragma unroll
            for (int mf = 0; mf < 2; mf++)
#pragma unroll
                for (int nf = 0; nf < 4; nf++)
                    mma_tf32(acc[mf][nf], a[mf][0], a[mf][1], a[mf][2], a[mf][3],
                             b[nf][0], b[nf][1]);
        }
        __syncthreads();
    }

#pragma unroll
    for (int mf = 0; mf < 2; mf++) {
        int row = m0 + wm * 32 + mf * 16 + g;
#pragma unroll
        for (int nf = 0; nf < 4; nf++) {
            int col = n0 + wn * 32 + nf * 8 + 2 * t;
            float b0 = bias[col], b1 = bias[col + 1];
            float v0 = acc[mf][nf][0] + b0;
            float v1 = acc[mf][nf][1] + b1;
            float v2 = acc[mf][nf][2] + b0;
            float v3 = acc[mf][nf][3] + b1;
            if (act) { v0 = lrelu(v0); v1 = lrelu(v1); v2 = lrelu(v2); v3 = lrelu(v3); }
            *reinterpret_cast<float2*>(&C[(size_t)row * NH + col])       = make_float2(v0, v1);
            *reinterpret_cast<float2*>(&C[(size_t)(row + 8) * NH + col]) = make_float2(v2, v3);
        }
    }
}

// ===========================================================================
extern "C" void kernel_launch(void* const* d_in, const int* in_sizes, int n_in,
                              void* d_out, int out_size)
{
    (void)in_sizes; (void)n_in; (void)out_size;
    const float* x    = (const float*)d_in[0];
    const float* y    = (const float*)d_in[1];
    const float* fc_w = (const float*)d_in[2];
    const float* fc_b = (const float*)d_in[3];
    const float* q_w  = (const float*)d_in[4];
    const float* q_b  = (const float*)d_in[5];
    const float* k_w  = (const float*)d_in[6];
    const float* k_b  = (const float*)d_in[7];
    const float* v_w  = (const float*)d_in[8];
    const float* v_b  = (const float*)d_in[9];
    float* out = (float*)d_out;

    float *p_xh, *p_q;
    cudaGetSymbolAddress((void**)&p_xh, g_xh);
    cudaGetSymbolAddress((void**)&p_q,  g_q);

    cudaFuncSetAttribute(fused, cudaFuncAttributeMaxDynamicSharedMemorySize, SMEM_FUSED);

    // 0) weights f32 -> fp16                        (~6 MB traffic)
    wcvt<<<256, 256>>>(fc_w, k_w, v_w);
    // 1) xh = lrelu(x @ fc_w^T + fc_b)              [2048, 512]  (tf32)
    gemm512_act<<<dim3(8, NB / 128), 256>>>(x, fc_w, fc_b, p_xh, 1);
    // 2) q = xh @ q_w^T + q_b                       [2048, 512]  (tf32)
    gemm512_act<<<dim3(8, NB / 128), 256>>>(p_xh, q_w, q_b, p_q, 0);
    // 3) fused per-batch: yh (SMEM-resident) + paired kv GEMM + softmax -> out
    fused<<<NB, NT_FUSED, SMEM_FUSED>>>(y, fc_b, k_b, v_b, out);
}

// round 17
// speedup vs baseline: 2.3202x; 1.0661x over previous
#include <cuda_runtime.h>
#include <cuda_fp16.h>
#include <cstdint>

#define ALPHA 0.2f

// Shapes (fixed by the problem)
#define NB   2048      // batch
#define NL   128       // neighbors
#define ND   512       // IN_DIM
#define NH   512       // HID

// Scratch (device globals: allocation-free by harness rules)
__device__ __align__(16) float  g_xh[NB * NH];        // 4 MB
__device__ __align__(16) float  g_q [NB * NH];        // 4 MB
__device__ __align__(16) __half g_fc16[ND * NH];      // 512 KB  fc_w fp16
__device__ __align__(16) __half g_kw16[NH * NH];      // 512 KB  k_w fp16
__device__ __align__(16) __half g_vw16[NH * NH];      // 512 KB  v_w fp16
__device__ __align__(16) __half g_qw16[NH * NH];      // 512 KB  q_w fp16

// ===========================================================================
// Helpers
// ===========================================================================
__device__ __forceinline__ float lrelu(float v) { return v > 0.0f ? v : ALPHA * v; }

__device__ __forceinline__ unsigned pack2(float a, float b) {
    __half2 h = __floats2half2_rn(a, b);
    return reinterpret_cast<unsigned&>(h);
}
__device__ __forceinline__ uint32_t smem_u32(const void* p) {
    uint32_t a;
    asm("{ .reg .u64 t; cvta.to.shared.u64 t, %1; cvt.u32.u64 %0, t; }" : "=r"(a) : "l"(p));
    return a;
}
__device__ __forceinline__ void ldmx4(uint32_t r[4], uint32_t addr) {
    asm volatile("ldmatrix.sync.aligned.m8n8.x4.shared.b16 {%0,%1,%2,%3}, [%4];"
                 : "=r"(r[0]), "=r"(r[1]), "=r"(r[2]), "=r"(r[3]) : "r"(addr));
}
__device__ __forceinline__ void mma_f16(float c[4], const uint32_t a[4],
                                        uint32_t b0, uint32_t b1) {
    asm volatile("mma.sync.aligned.m16n8k16.row.col.f32.f16.f16.f32 "
                 "{%0,%1,%2,%3}, {%4,%5,%6,%7}, {%8,%9}, {%0,%1,%2,%3};"
                 : "+f"(c[0]), "+f"(c[1]), "+f"(c[2]), "+f"(c[3])
                 : "r"(a[0]), "r"(a[1]), "r"(a[2]), "r"(a[3]), "r"(b0), "r"(b1));
}
__device__ __forceinline__ void cpa16(uint32_t dst, const void* src) {
    asm volatile("cp.async.cg.shared.global [%0], [%1], 16;" :: "r"(dst), "l"(src));
}
#define CP_COMMIT asm volatile("cp.async.commit_group;" ::: "memory")
#define CP_WAIT1  asm volatile("cp.async.wait_group 1;" ::: "memory")
#define CP_WAIT0  asm volatile("cp.async.wait_group 0;" ::: "memory")

// 16B-segment swizzle (128B rows, 8 segments): seg' = seg ^ (row & 7)
// ldmatrix address for an 8x8 fp16 tile at (rowbase, colbyte)
__device__ __forceinline__ uint32_t ldm_addr(uint32_t base, int rowbase, int colbyte, int lane) {
    int mi = lane >> 3;
    int r  = rowbase + (mi & 1) * 8 + (lane & 7);
    unsigned off = (unsigned)(r * 128 + colbyte + (mi >> 1) * 16);
    return base + (off ^ ((off >> 3) & 0x70));
}

// Fused-kernel SMEM layout (offsets from 128B-aligned base):
//   YH tiles: 8 x [128][64] fp16 swizzled, tile k at k*16384      [0, 131072)
//   Phase 1: B bufs (x3) at 131072+i*16384, A bufs (x3) at 180224+i*16384
//   Phase 2: kv pair bufs (x3, 32 KB each) at 131072+i*32768      [131072, 229376)
//   sred2 (4 KB softmax scratch) ALIASES pair buf 2 (dead during epilogue).
#define YH_OFF(k)   ((k) * 16384)
#define B_OFF(i)    (131072 + (i) * 16384)
#define A_OFF(i)    (180224 + (i) * 16384)
#define PAIR_OFF(i) (131072 + (i) * 32768)
#define SRED_OFF    PAIR_OFF(2)
#define SMEM_FUSED  (229376 + 128)

#define NT_FUSED 512   // 16 warps

// Small-GEMM SMEM layout: A bufs 3 x 8 KB, B bufs 3 x 16 KB
#define GA_OFF(i)  ((i) * 8192)
#define GB_OFF(i)  (24576 + (i) * 16384)
#define SMEM_G     (73728 + 128)

// ===========================================================================
// Weight pre-convert: fc_w / k_w / v_w / q_w  f32 -> fp16
// ===========================================================================
__global__ void wcvt(const float* __restrict__ fc, const float* __restrict__ kw,
                     const float* __restrict__ vw, const float* __restrict__ qw) {
    int i = blockIdx.x * blockDim.x + threadIdx.x;     // 0..65535, 4 floats each
    float4 a = *reinterpret_cast<const float4*>(fc + (size_t)i * 4);
    float4 b = *reinterpret_cast<const float4*>(kw + (size_t)i * 4);
    float4 c = *reinterpret_cast<const float4*>(vw + (size_t)i * 4);
    float4 d = *reinterpret_cast<const float4*>(qw + (size_t)i * 4);
    *reinterpret_cast<uint2*>(&g_fc16[(size_t)i * 4]) = make_uint2(pack2(a.x, a.y), pack2(a.z, a.w));
    *reinterpret_cast<uint2*>(&g_kw16[(size_t)i * 4]) = make_uint2(pack2(b.x, b.y), pack2(b.z, b.w));
    *reinterpret_cast<uint2*>(&g_vw16[(size_t)i * 4]) = make_uint2(pack2(c.x, c.y), pack2(c.z, c.w));
    *reinterpret_cast<uint2*>(&g_qw16[(size_t)i * 4]) = make_uint2(pack2(d.x, d.y), pack2(d.z, d.w));
}

// ===========================================================================
// Small GEMM (fp16 mma): C[M,512] = act(A_f32 @ W16^T + bias)
// CTA tile 64(M) x 128(N), 256 threads (8 warps as 2x4, warp tile 32x32).
// grid = (4 n-tiles, 32 m-tiles). 3-stage cp.async pipeline for B.
// ===========================================================================
__global__ __launch_bounds__(256) void gemm512h(
    const float* __restrict__ A, const __half* __restrict__ W16,
    const float* __restrict__ bias, float* __restrict__ C, int act)
{
    extern __shared__ char smem_raw[];
    char* sm = smem_raw + ((128 - ((uintptr_t)smem_raw & 127)) & 127);
    const uint32_t sb = smem_u32(sm);

    const int tid = threadIdx.x, warp = tid >> 5, lane = tid & 31;
    const int g = lane >> 2, t = lane & 3;
    const int wm = warp & 1, wn = warp >> 1;            // 2 x 4 warp grid
    const int m0 = blockIdx.y * 64;
    const int n0 = blockIdx.x * 128;
    const float* Ab = A + (size_t)m0 * ND;

    float acc[2][4][4];
#pragma unroll
    for (int mf = 0; mf < 2; mf++)
#pragma unroll
        for (int nf = 0; nf < 4; nf++)
#pragma unroll
            for (int i = 0; i < 4; i++) acc[mf][nf][i] = 0.0f;

    uint4 ra[2];
    auto ldgA = [&](int c) {
#pragma unroll
        for (int i = 0; i < 2; i++) {
            int idx = i * 256 + tid;
            int r = idx >> 3, s = idx & 7;              // r in 0..63
            const float* p = Ab + (size_t)r * ND + c * 64 + s * 8;
            float4 a0 = *reinterpret_cast<const float4*>(p);
            float4 a1 = *reinterpret_cast<const float4*>(p + 4);
            ra[i] = make_uint4(pack2(a0.x, a0.y), pack2(a0.z, a0.w),
                               pack2(a1.x, a1.y), pack2(a1.z, a1.w));
        }
    };
    auto stsA = [&](int buf) {
#pragma unroll
        for (int i = 0; i < 2; i++) {
            int idx = i * 256 + tid;
            int r = idx >> 3, s = idx & 7;
            unsigned off = (unsigned)(r * 128 + ((s ^ (r & 7)) * 16));
            *reinterpret_cast<uint4*>(sm + GA_OFF(buf) + off) = ra[i];
        }
    };
    auto cpB = [&](int buf, int c) {
#pragma unroll
        for (int i = 0; i < 4; i++) {
            int idx = i * 256 + tid;
            int r = idx >> 3, s = idx & 7;              // r in 0..127
            const __half* src = W16 + (size_t)(n0 + r) * NH + c * 64 + s * 8;
            unsigned off = (unsigned)(r * 128 + ((s ^ (r & 7)) * 16));
            cpa16(sb + GB_OFF(buf) + off, src);
        }
    };
    auto mmac = [&](uint32_t Abase, uint32_t Bbase) {
#pragma unroll
        for (int ks = 0; ks < 4; ks++) {
            uint32_t a[2][4], b[2][4];
#pragma unroll
            for (int mf = 0; mf < 2; mf++)
                ldmx4(a[mf], ldm_addr(Abase, wm * 32 + mf * 16, ks * 32, lane));
#pragma unroll
            for (int np = 0; np < 2; np++)
                ldmx4(b[np], ldm_addr(Bbase, wn * 32 + np * 16, ks * 32, lane));
#pragma unroll
            for (int mf = 0; mf < 2; mf++)
#pragma unroll
                for (int nf = 0; nf < 4; nf++)
                    mma_f16(acc[mf][nf], a[mf],
                            b[nf >> 1][nf & 1], b[nf >> 1][(nf & 1) + 2]);
        }
    };

    ldgA(0); stsA(0); cpB(0, 0); CP_COMMIT;
    ldgA(1); stsA(1); cpB(1, 1); CP_COMMIT;
    ldgA(2);
    for (int c = 0; c < 8; c++) {
        if (c < 7) { CP_WAIT1; } else { CP_WAIT0; }
        __syncthreads();
        if (c + 2 < 8) { stsA((c + 2) % 3); cpB((c + 2) % 3, c + 2); CP_COMMIT; }
        if (c + 3 < 8) ldgA(c + 3);
        mmac(sb + GA_OFF(c % 3), sb + GB_OFF(c % 3));
    }

#pragma unroll
    for (int mf = 0; mf < 2; mf++) {
        int row = m0 + wm * 32 + mf * 16 + g;
#pragma unroll
        for (int nf = 0; nf < 4; nf++) {
            int col = n0 + wn * 32 + nf * 8 + 2 * t;
            float b0 = bias[col], b1 = bias[col + 1];
            float v0 = acc[mf][nf][0] + b0;
            float v1 = acc[mf][nf][1] + b1;
            float v2 = acc[mf][nf][2] + b0;
            float v3 = acc[mf][nf][3] + b1;
            if (act) { v0 = lrelu(v0); v1 = lrelu(v1); v2 = lrelu(v2); v3 = lrelu(v3); }
            *reinterpret_cast<float2*>(&C[(size_t)row * NH + col])       = make_float2(v0, v1);
            *reinterpret_cast<float2*>(&C[(size_t)(row + 8) * NH + col]) = make_float2(v2, v3);
        }
    }
}

// ===========================================================================
// Fused per-batch kernel (512 threads, 16 warps as 4x4), overlap-restructured:
//   Phase 1: yh_b = lrelu(y_b @ fc_w^T + fc_b) -> SMEM fp16 (swizzled tiles)
//   Phase 2: 4x { paired kv chunk GEMM + register softmax }
// All nt/hp prologues are folded behind the previous post-mainloop barrier so
// cp.async prefetch overlaps the epilogues.
// ===========================================================================
__global__ __launch_bounds__(NT_FUSED, 1) void fused(
    const float* __restrict__ y, const float* __restrict__ fc_b,
    const float* __restrict__ kb, const float* __restrict__ vb,
    float* __restrict__ out)
{
    extern __shared__ char smem_raw[];
    char* sm = smem_raw + ((128 - ((uintptr_t)smem_raw & 127)) & 127);
    const uint32_t sb = smem_u32(sm);

    const int tid = threadIdx.x, warp = tid >> 5, lane = tid & 31;
    const int g = lane >> 2, t = lane & 3;
    const int wm = warp & 3, wn = warp >> 2;            // 4 x 4 warp grid
    const int bb = blockIdx.x;
    const float* yb = y + (size_t)bb * NL * ND;

    float acc2[2][2][4][4];
    uint4 ra[2];

    auto ldgA = [&](int c) {
#pragma unroll
        for (int i = 0; i < 2; i++) {
            int idx = i * NT_FUSED + tid;
            int r = idx >> 3, s = idx & 7;
            const float* p = yb + (size_t)r * ND + c * 64 + s * 8;
            float4 a0 = *reinterpret_cast<const float4*>(p);
            float4 a1 = *reinterpret_cast<const float4*>(p + 4);
            ra[i] = make_uint4(pack2(a0.x, a0.y), pack2(a0.z, a0.w),
                               pack2(a1.x, a1.y), pack2(a1.z, a1.w));
        }
    };
    auto stsA = [&](int buf) {
#pragma unroll
        for (int i = 0; i < 2; i++) {
            int idx = i * NT_FUSED + tid;
            int r = idx >> 3, s = idx & 7;
            unsigned off = (unsigned)(r * 128 + ((s ^ (r & 7)) * 16));
            *reinterpret_cast<uint4*>(sm + A_OFF(buf) + off) = ra[i];
        }
    };
    auto cpB1 = [&](int buf, int c, int nt) {
#pragma unroll
        for (int i = 0; i < 2; i++) {
            int idx = i * NT_FUSED + tid;
            int r = idx >> 3, s = idx & 7;
            const __half* src = g_fc16 + (size_t)(nt * 128 + r) * NH + c * 64 + s * 8;
            unsigned off = (unsigned)(r * 128 + ((s ^ (r & 7)) * 16));
            cpa16(sb + B_OFF(buf) + off, src);
        }
    };
    auto cpB2 = [&](int buf, int c, int hp) {
#pragma unroll
        for (int i = 0; i < 4; i++) {
            int idx = i * NT_FUSED + tid;
            int r = idx >> 3, s = idx & 7;       // r in 0..255
            int u = r >> 7, rr = r & 127;
            int f = hp * 128 + u * 64 + (rr >> 1);
            const __half* base = (rr & 1) ? g_vw16 : g_kw16;
            const __half* src = base + (size_t)f * NH + c * 64 + s * 8;
            unsigned off = (unsigned)(rr * 128 + ((s ^ (rr & 7)) * 16));
            cpa16(sb + PAIR_OFF(buf) + u * 16384 + off, src);
        }
    };
    auto mmac1 = [&](uint32_t Abase, uint32_t Bbase) {
#pragma unroll
        for (int ks = 0; ks < 4; ks++) {
            uint32_t a[2][4], b[2][4];
#pragma unroll
            for (int mf = 0; mf < 2; mf++)
                ldmx4(a[mf], ldm_addr(Abase, wm * 32 + mf * 16, ks * 32, lane));
#pragma unroll
            for (int np = 0; np < 2; np++)
                ldmx4(b[np], ldm_addr(Bbase, wn * 32 + np * 16, ks * 32, lane));
#pragma unroll
            for (int mf = 0; mf < 2; mf++)
#pragma unroll
                for (int nf = 0; nf < 4; nf++)
                    mma_f16(acc2[0][mf][nf], a[mf],
                            b[nf >> 1][nf & 1], b[nf >> 1][(nf & 1) + 2]);
        }
    };
    auto mmac2 = [&](uint32_t Abase, uint32_t Bbase) {
#pragma unroll
        for (int ks = 0; ks < 4; ks++) {
            uint32_t a[2][4];
#pragma unroll
            for (int mf = 0; mf < 2; mf++)
                ldmx4(a[mf], ldm_addr(Abase, wm * 32 + mf * 16, ks * 32, lane));
#pragma unroll
            for (int u = 0; u < 2; u++) {
                uint32_t b[2][4];
#pragma unroll
                for (int np = 0; np < 2; np++)
                    ldmx4(b[np], ldm_addr(Bbase + u * 16384, wn * 32 + np * 16,
                                          ks * 32, lane));
#pragma unroll
                for (int mf = 0; mf < 2; mf++)
#pragma unroll
                    for (int nf = 0; nf < 4; nf++)
                        mma_f16(acc2[u][mf][nf], a[mf],
                                b[nf >> 1][nf & 1], b[nf >> 1][(nf & 1) + 2]);
            }
        }
    };

    // ---------------- Phase 1: yh_b -> SMEM ----------------
    ldgA(0); stsA(0); cpB1(0, 0, 0); CP_COMMIT;
    ldgA(1); stsA(1); cpB1(1, 1, 0); CP_COMMIT;
    ldgA(2);
    for (int nt = 0; nt < 4; nt++) {
#pragma unroll
        for (int mf = 0; mf < 2; mf++)
#pragma unroll
            for (int nf = 0; nf < 4; nf++)
#pragma unroll
                for (int i = 0; i < 4; i++) acc2[0][mf][nf][i] = 0.0f;

        for (int c = 0; c < 8; c++) {
            if (c < 7) { CP_WAIT1; } else { CP_WAIT0; }
            __syncthreads();
            if (c + 2 < 8) { stsA((c + 2) % 3); cpB1((c + 2) % 3, c + 2, nt); CP_COMMIT; }
            if (c + 3 < 8) ldgA(c + 3);
            mmac1(sb + A_OFF(c % 3), sb + B_OFF(c % 3));
        }
        __syncthreads();   // all mma reads of all bufs done

        // Fold next block's prologue here so cp.async overlaps the epilogue.
        if (nt < 3) {
            ldgA(0); stsA(0); cpB1(0, 0, nt + 1); CP_COMMIT;
            ldgA(1); stsA(1); cpB1(1, 1, nt + 1); CP_COMMIT;
            ldgA(2);
        } else {
            cpB2(0, 0, 0); CP_COMMIT;    // pair buf 0 aliases B bufs 0-1 (reads done)
            cpB2(1, 1, 0); CP_COMMIT;    // pair buf 1 aliases B buf 2 + A buf 0
        }

        // epilogue: bias + lrelu -> fp16 into YH tiles (swizzled)
#pragma unroll
        for (int mf = 0; mf < 2; mf++) {
            int row = wm * 32 + mf * 16 + g;
#pragma unroll
            for (int nf = 0; nf < 4; nf++) {
                int colg = nt * 128 + wn * 32 + nf * 8 + 2 * t;
                int tile = colg >> 6, cc = colg & 63;
                float b0 = fc_b[colg], b1 = fc_b[colg + 1];
                __half2 h0 = __floats2half2_rn(lrelu(acc2[0][mf][nf][0] + b0),
                                               lrelu(acc2[0][mf][nf][1] + b1));
                __half2 h1 = __floats2half2_rn(lrelu(acc2[0][mf][nf][2] + b0),
                                               lrelu(acc2[0][mf][nf][3] + b1));
                unsigned o0 = (unsigned)(row * 128 + cc * 2);
                o0 ^= (o0 >> 3) & 0x70;
                *reinterpret_cast<__half2*>(sm + YH_OFF(tile) + o0) = h0;
                unsigned o1 = (unsigned)((row + 8) * 128 + cc * 2);
                o1 ^= (o1 >> 3) & 0x70;
                *reinterpret_cast<__half2*>(sm + YH_OFF(tile) + o1) = h1;
            }
        }
        // No barrier: next mainloop's c=0 barrier orders stsA/epilogue writes.
    }

    // ---------------- Phase 2: paired kv chunks + register softmax ----------
    float* sred2 = reinterpret_cast<float*>(sm + SRED_OFF);   // aliases pair buf 2

    for (int hp = 0; hp < 4; hp++) {
#pragma unroll
        for (int u = 0; u < 2; u++)
#pragma unroll
            for (int mf = 0; mf < 2; mf++)
#pragma unroll
                for (int nf = 0; nf < 4; nf++)
#pragma unroll
                    for (int i = 0; i < 4; i++) acc2[u][mf][nf][i] = 0.0f;

        // Prefetch epilogue scalars so gmem latency hides under the mainloop.
        float qv[2][4], kbv[2][4], vbv[2][4];
#pragma unroll
        for (int u = 0; u < 2; u++)
#pragma unroll
            for (int nf = 0; nf < 4; nf++) {
                int h = hp * 128 + u * 64 + wn * 16 + nf * 4 + t;
                qv[u][nf]  = g_q[(size_t)bb * NH + h];
                kbv[u][nf] = kb[h];
                vbv[u][nf] = vb[h];
            }
        float xh_pref = 0.0f;
        if (tid < 128) xh_pref = g_xh[(size_t)bb * NH + hp * 128 + tid];

        for (int c = 0; c < 8; c++) {
            if (c < 7) { CP_WAIT1; } else { CP_WAIT0; }
            __syncthreads();
            if (c + 2 < 8) { cpB2((c + 2) % 3, c + 2, hp); CP_COMMIT; }
            mmac2(sb + YH_OFF(c), sb + PAIR_OFF(c % 3));
        }

        // Register reduction (max-free softmax: |att| << 1, exp safe in fp32;
        // z and h scale identically so the quotient is exact).
        float zp[2][4], hp_[2][4];
#pragma unroll
        for (int u = 0; u < 2; u++)
#pragma unroll
            for (int nf = 0; nf < 4; nf++) {
                float z = 0.0f, hs = 0.0f;
#pragma unroll
                for (int mf = 0; mf < 2; mf++) {
                    float e0 = __expf((acc2[u][mf][nf][0] + kbv[u][nf]) * qv[u][nf]);
                    z += e0;
                    hs += lrelu((acc2[u][mf][nf][1] + vbv[u][nf]) * e0);
                    float e1 = __expf((acc2[u][mf][nf][2] + kbv[u][nf]) * qv[u][nf]);
                    z += e1;
                    hs += lrelu((acc2[u][mf][nf][3] + vbv[u][nf]) * e1);
                }
                z  += __shfl_xor_sync(0xffffffffu, z, 4);
                z  += __shfl_xor_sync(0xffffffffu, z, 8);
                z  += __shfl_xor_sync(0xffffffffu, z, 16);
                hs += __shfl_xor_sync(0xffffffffu, hs, 4);
                hs += __shfl_xor_sync(0xffffffffu, hs, 8);
                hs += __shfl_xor_sync(0xffffffffu, hs, 16);
                zp[u][nf] = z; hp_[u][nf] = hs;
            }
        __syncthreads();   // all mma reads done: pair bufs 0-1 and sred2 free

        // Next hp's first two prefetches overlap the epilogue below.
        if (hp < 3) { cpB2(0, 0, hp + 1); CP_COMMIT; cpB2(1, 1, hp + 1); CP_COMMIT; }

        if (g == 0) {
#pragma unroll
            for (int u = 0; u < 2; u++)
#pragma unroll
                for (int nf = 0; nf < 4; nf++) {
                    int f = wn * 16 + nf * 4 + t;
                    sred2[((wm * 2 + u) * 64 + f) * 2]     = zp[u][nf];
                    sred2[((wm * 2 + u) * 64 + f) * 2 + 1] = hp_[u][nf];
                }
        }
        __syncthreads();

        if (tid < 128) {
            int u = tid >> 6, f = tid & 63;
            float z = 0.0f, hs = 0.0f;
#pragma unroll
            for (int w = 0; w < 4; w++) {
                z  += sred2[((w * 2 + u) * 64 + f) * 2];
                hs += sred2[((w * 2 + u) * 64 + f) * 2 + 1];
            }
            out[(size_t)bb * NH + hp * 128 + tid] = (xh_pref + hs / z) * 0.5f;
        }
        // Next hp's c=0 barrier orders sred2 reads before its rewrite.
    }
}

// ===========================================================================
extern "C" void kernel_launch(void* const* d_in, const int* in_sizes, int n_in,
                              void* d_out, int out_size)
{
    (void)in_sizes; (void)n_in; (void)out_size;
    const float* x    = (const float*)d_in[0];
    const float* y    = (const float*)d_in[1];
    const float* fc_w = (const float*)d_in[2];
    const float* fc_b = (const float*)d_in[3];
    const float* q_w  = (const float*)d_in[4];
    const float* q_b  = (const float*)d_in[5];
    const float* k_w  = (const float*)d_in[6];
    const float* k_b  = (const float*)d_in[7];
    const float* v_w  = (const float*)d_in[8];
    const float* v_b  = (const float*)d_in[9];
    float* out = (float*)d_out;

    float  *p_xh, *p_q;
    __half *p_fc16, *p_qw16;
    cudaGetSymbolAddress((void**)&p_xh,   g_xh);
    cudaGetSymbolAddress((void**)&p_q,    g_q);
    cudaGetSymbolAddress((void**)&p_fc16, g_fc16);
    cudaGetSymbolAddress((void**)&p_qw16, g_qw16);

    cudaFuncSetAttribute(fused,    cudaFuncAttributeMaxDynamicSharedMemorySize, SMEM_FUSED);
    cudaFuncSetAttribute(gemm512h, cudaFuncAttributeMaxDynamicSharedMemorySize, SMEM_G);

    // 0) weights f32 -> fp16
    wcvt<<<256, 256>>>(fc_w, k_w, v_w, q_w);
    // 1) xh = lrelu(x @ fc_w^T + fc_b)              [2048, 512]  (fp16 mma)
    gemm512h<<<dim3(4, 32), 256, SMEM_G>>>(x, p_fc16, fc_b, p_xh, 1);
    // 2) q = xh @ q_w^T + q_b                       [2048, 512]  (fp16 mma)
    gemm512h<<<dim3(4, 32), 256, SMEM_G>>>(p_xh, p_qw16, q_b, p_q, 0);
    // 3) fused per-batch: yh (SMEM-resident) + paired kv GEMM + softmax -> out
    fused<<<NB, NT_FUSED, SMEM_FUSED>>>(y, fc_b, k_b, v_b, out);
}